// round 12
// baseline (speedup 1.0000x reference)
#include <cuda_runtime.h>
#include <cuda_bf16.h>
#include <math.h>
#include <stdint.h>

#define R_TOT 16384
#define S_LEN 4096
#define D_DIM 128
#define K_LNK 13
#define M_NET 12

typedef unsigned int u32;
typedef unsigned long long u64;

// ---------------- scratch (static device memory only) ----------------------
__device__ __nv_bfloat16 g_Xhi[R_TOT * D_DIM];          // X hi, row-major
__device__ __nv_bfloat16 g_Xlo[R_TOT * D_DIM];          // X lo
__device__ __nv_bfloat16 g_B1hi[13 * 128 * 128];        // W1^T [net][n][k]
__device__ __nv_bfloat16 g_B1lo[13 * 128 * 128];
__device__ __nv_bfloat16 g_B2ghi[128 * 128];            // gW2^T [n][k]
__device__ __nv_bfloat16 g_B2glo[128 * 128];
__device__ __nv_bfloat16 g_B2fhi[12 * 16 * 128];        // fW2^T padded N=16
__device__ float g_Vres[R_TOT * D_DIM];                 // fp32 residual (exact)
__device__ __nv_bfloat16 g_VresBf[R_TOT * D_DIM];       // bf16 residual mirror
__device__ __nv_bfloat16 g_Vbf0[R_TOT * D_DIM];         // bf16 V ping
__device__ __nv_bfloat16 g_Vbf1[R_TOT * D_DIM];         // bf16 V pong
__device__ float g_Wall[M_NET * R_TOT * K_LNK];

// ---------------- helpers ---------------------------------------------------
__device__ __forceinline__ u32 smem_u32(const void* p) {
    u32 a;
    asm("{ .reg .u64 t; cvta.to.shared.u64 t, %1; cvt.u32.u64 %0, t; }"
        : "=r"(a) : "l"(p));
    return a;
}
__device__ __forceinline__ void ldsm4(u32* r, u32 addr) {
    asm volatile("ldmatrix.sync.aligned.m8n8.x4.shared.b16 {%0,%1,%2,%3}, [%4];"
        : "=r"(r[0]), "=r"(r[1]), "=r"(r[2]), "=r"(r[3]) : "r"(addr));
}
__device__ __forceinline__ void mma16816(float* d, const u32* a, const u32* b) {
    asm volatile(
        "mma.sync.aligned.m16n8k16.row.col.f32.bf16.bf16.f32 "
        "{%0,%1,%2,%3}, {%4,%5,%6,%7}, {%8,%9}, {%0,%1,%2,%3};"
        : "+f"(d[0]), "+f"(d[1]), "+f"(d[2]), "+f"(d[3])
        : "r"(a[0]), "r"(a[1]), "r"(a[2]), "r"(a[3]), "r"(b[0]), "r"(b[1]));
}
// swizzled byte address of 16B unit (r, c16) in a [rows][128]bf16 smem tile
__device__ __forceinline__ u32 sw_addr(u32 base, int r, int c16) {
    return base + (u32)(((r << 4) + (c16 ^ (r & 7))) << 4);
}
__device__ __forceinline__ void bf_split(float v, unsigned short& h,
                                         unsigned short& l) {
    __nv_bfloat16 hb = __float2bfloat16(v);
    __nv_bfloat16 lb = __float2bfloat16(v - __bfloat162float(hb));
    h = __bfloat16_as_ushort(hb);
    l = __bfloat16_as_ushort(lb);
}
// pack two fp32 -> bf16x2 (lo arg in low half = memory-first element)
__device__ __forceinline__ u32 pack_bf16x2(float lo, float hi) {
    u32 r;
    asm("cvt.rn.bf16x2.f32 %0, %1, %2;" : "=r"(r) : "f"(hi), "f"(lo));
    return r;
}
__device__ __forceinline__ void fma_bf2(u32& d, u32 a, u32 b) {
    asm("fma.rn.bf16x2 %0, %1, %2, %0;" : "+r"(d) : "r"(a), "r"(b));
}
__device__ __forceinline__ u32 add_bf2(u32 a, u32 b) {
    u32 r;
    asm("add.rn.bf16x2 %0, %1, %2;" : "=r"(r) : "r"(a), "r"(b));
    return r;
}
__device__ __forceinline__ float gelu_exact(float x) {
    return 0.5f * x * (1.0f + erff(x * 0.70710678118654752440f));
}

// ---------------------------------------------------------------------------
// Prep: transpose + bf16-split weights into [n][k] row-major hi/lo.
// ---------------------------------------------------------------------------
#define PREP_A (13 * 128 * 64)
#define PREP_B (128 * 64)
#define PREP_C (12 * 16 * 64)
#define PREP_TOT (PREP_A + PREP_B + PREP_C)

__global__ void k_prep(const float* __restrict__ gW1,
                       const float* __restrict__ gW2,
                       const float* __restrict__ fW1,
                       const float* __restrict__ fW2) {
    int t = blockIdx.x * blockDim.x + threadIdx.x;
    if (t >= PREP_TOT) return;

    float w0, w1;
    if (t < PREP_A) {
        int net = t >> 13;
        int r = t & 8191;
        int n = r >> 6, k = (r & 63) * 2;
        const float* W1 = (net == 0) ? gW1 : fW1 + (size_t)(net - 1) * 128 * 128;
        w0 = W1[k * 128 + n];
        w1 = W1[(k + 1) * 128 + n];
        int widx = (net * 128 + n) * 64 + (k >> 1);
        unsigned short h0, l0, h1, l1;
        bf_split(w0, h0, l0); bf_split(w1, h1, l1);
        ((u32*)g_B1hi)[widx] = (u32)h0 | ((u32)h1 << 16);
        ((u32*)g_B1lo)[widx] = (u32)l0 | ((u32)l1 << 16);
    } else if (t < PREP_A + PREP_B) {
        int r = t - PREP_A;
        int n = r >> 6, k = (r & 63) * 2;
        w0 = gW2[k * 128 + n];
        w1 = gW2[(k + 1) * 128 + n];
        int widx = n * 64 + (k >> 1);
        unsigned short h0, l0, h1, l1;
        bf_split(w0, h0, l0); bf_split(w1, h1, l1);
        ((u32*)g_B2ghi)[widx] = (u32)h0 | ((u32)h1 << 16);
        ((u32*)g_B2glo)[widx] = (u32)l0 | ((u32)l1 << 16);
    } else {
        int r = t - PREP_A - PREP_B;
        int net = r >> 10;
        int rr = r & 1023;
        int n = rr >> 6, k = (rr & 63) * 2;
        w0 = (n < 13) ? fW2[(size_t)net * 128 * 13 + k * 13 + n] : 0.0f;
        w1 = (n < 13) ? fW2[(size_t)net * 128 * 13 + (k + 1) * 13 + n] : 0.0f;
        ((u32*)g_B2fhi)[(net * 16 + n) * 64 + (k >> 1)] =
            pack_bf16x2(w0, w1);
    }
}

// ---------------------------------------------------------------------------
// Embed: x = emb[data] + apc -> bf16 hi/lo row-major.
// ---------------------------------------------------------------------------
__global__ void k_embed(const int* __restrict__ data,
                        const float* __restrict__ emb,
                        const float* __restrict__ apc) {
    int idx = blockIdx.x * blockDim.x + threadIdx.x;   // R_TOT*16 threads
    int row = idx >> 4;
    int g8 = idx & 15;
    int tok = data[row];
    int s = row & (S_LEN - 1);
    float4 e0 = ((const float4*)emb)[tok * 32 + g8 * 2];
    float4 e1 = ((const float4*)emb)[tok * 32 + g8 * 2 + 1];
    float4 a0 = ((const float4*)apc)[s * 32 + g8 * 2];
    float4 a1 = ((const float4*)apc)[s * 32 + g8 * 2 + 1];
    float v[8] = {e0.x + a0.x, e0.y + a0.y, e0.z + a0.z, e0.w + a0.w,
                  e1.x + a1.x, e1.y + a1.y, e1.z + a1.z, e1.w + a1.w};
    u32 hp[4], lp[4];
    #pragma unroll
    for (int p = 0; p < 4; ++p) {
        unsigned short h0, l0, h1, l1;
        bf_split(v[2 * p], h0, l0);
        bf_split(v[2 * p + 1], h1, l1);
        hp[p] = (u32)h0 | ((u32)h1 << 16);
        lp[p] = (u32)l0 | ((u32)l1 << 16);
    }
    ((uint4*)g_Xhi)[row * 16 + g8] = make_uint4(hp[0], hp[1], hp[2], hp[3]);
    ((uint4*)g_Xlo)[row * 16 + g8] = make_uint4(lp[0], lp[1], lp[2], lp[3]);
}

// ---------------------------------------------------------------------------
// k_mlp: warp-MMA fused 2-layer MLP.
// m==0 (g-net): 3-term bf16 hi/lo split (feeds the fp32 backbone).
// m>=1 (f-nets): single-term plain bf16.
// grid = (128 row-tiles, 13 nets), 512 threads (16 warps, warp tile 32x32).
// ---------------------------------------------------------------------------
#define SM_W1HI  0
#define SM_W1LO  32768
#define SM_XHHI  65536
#define SM_XHLO  98304
#define SM_F2HI  131072
#define SM_B1S   139264
#define SM_B2S   139776
#define SMEM_MLP 140288

extern __shared__ char smc[];

__global__ void __launch_bounds__(512, 1) k_mlp(
    const float* __restrict__ gb1, const float* __restrict__ gb2,
    const float* __restrict__ fb1, const float* __restrict__ fb2) {
    const int tid = threadIdx.x;
    const int lane = tid & 31;
    const int wid = tid >> 5;
    const int m = blockIdx.y;
    const int row0 = blockIdx.x * 128;
    const u32 sbase = smem_u32(smc);
    float* b1s = (float*)(smc + SM_B1S);
    float* b2s = (float*)(smc + SM_B2S);

    // ---- stage into swizzled smem (lo regions only for g-net) ----
    {
        const uint4* s1h = (const uint4*)g_B1hi + m * 2048;
        const uint4* s1l = (const uint4*)g_B1lo + m * 2048;
        const uint4* sxh = (const uint4*)g_Xhi + row0 * 16;
        const uint4* sxl = (const uint4*)g_Xlo + row0 * 16;
        #pragma unroll
        for (int p = 0; p < 4; ++p) {
            int q = tid + p * 512;
            int r = q >> 4, c16 = q & 15;
            u32 d = (u32)(((r << 4) + (c16 ^ (r & 7))) << 4);
            *(uint4*)(smc + SM_W1HI + d) = s1h[q];
            *(uint4*)(smc + SM_XHHI + d) = sxh[q];
            if (m == 0) {
                *(uint4*)(smc + SM_W1LO + d) = s1l[q];
                *(uint4*)(smc + SM_XHLO + d) = sxl[q];
            }
        }
    }
    if (m > 0) {
        const uint4* sfh = (const uint4*)g_B2fhi + (m - 1) * 256;
        if (tid < 256) {
            int r = tid >> 4, c16 = tid & 15;
            u32 d = (u32)(((r << 4) + (c16 ^ (r & 7))) << 4);
            *(uint4*)(smc + SM_F2HI + d) = sfh[tid];
        }
        if (tid < 128) b1s[tid] = fb1[(m - 1) * 128 + tid];
        if (tid < 16)  b2s[tid] = (tid < 13) ? fb2[(m - 1) * 13 + tid] : 0.0f;
    } else {
        if (tid < 128) { b1s[tid] = gb1[tid]; b2s[tid] = gb2[tid]; }
    }
    __syncthreads();

    // fragment lane offsets
    const int a_ro = (lane & 7) + (lane & 8);
    const int a_co = lane >> 4;
    const int b_ro = (lane & 7) + ((lane >> 1) & 8);
    const int b_co = (lane >> 3) & 1;
    const int tq = lane >> 2;
    const int tr = (lane & 3) * 2;

    const int wm = (wid & 3) * 32;    // warp M offset
    const int wn = (wid >> 2) * 32;   // warp N offset

    // ================= Layer 1: H = gelu(X @ W1 + b1) ======================
    float acc[2][4][4];
    #pragma unroll
    for (int i = 0; i < 2; ++i)
        #pragma unroll
        for (int j = 0; j < 4; ++j)
            #pragma unroll
            for (int q = 0; q < 4; ++q) acc[i][j][q] = 0.0f;

    if (m == 0) {
        #pragma unroll
        for (int k = 0; k < 8; ++k) {
            const int kc = k * 2;
            u32 ah[2][4], al[2][4], bh[2][4], bl[2][4];
            #pragma unroll
            for (int mt = 0; mt < 2; ++mt) {
                int r = wm + mt * 16 + a_ro;
                ldsm4(ah[mt], sw_addr(sbase + SM_XHHI, r, kc + a_co));
                ldsm4(al[mt], sw_addr(sbase + SM_XHLO, r, kc + a_co));
            }
            #pragma unroll
            for (int ng = 0; ng < 2; ++ng) {
                int r = wn + ng * 16 + b_ro;
                ldsm4(bh[ng], sw_addr(sbase + SM_W1HI, r, kc + b_co));
                ldsm4(bl[ng], sw_addr(sbase + SM_W1LO, r, kc + b_co));
            }
            #pragma unroll
            for (int mt = 0; mt < 2; ++mt)
                #pragma unroll
                for (int ng = 0; ng < 2; ++ng) {
                    mma16816(acc[mt][2 * ng],     ah[mt], &bh[ng][0]);
                    mma16816(acc[mt][2 * ng + 1], ah[mt], &bh[ng][2]);
                    mma16816(acc[mt][2 * ng],     ah[mt], &bl[ng][0]);
                    mma16816(acc[mt][2 * ng + 1], ah[mt], &bl[ng][2]);
                    mma16816(acc[mt][2 * ng],     al[mt], &bh[ng][0]);
                    mma16816(acc[mt][2 * ng + 1], al[mt], &bh[ng][2]);
                }
        }
    } else {
        #pragma unroll
        for (int k = 0; k < 8; ++k) {
            const int kc = k * 2;
            u32 ah[2][4], bh[2][4];
            #pragma unroll
            for (int mt = 0; mt < 2; ++mt)
                ldsm4(ah[mt], sw_addr(sbase + SM_XHHI, wm + mt * 16 + a_ro, kc + a_co));
            #pragma unroll
            for (int ng = 0; ng < 2; ++ng)
                ldsm4(bh[ng], sw_addr(sbase + SM_W1HI, wn + ng * 16 + b_ro, kc + b_co));
            #pragma unroll
            for (int mt = 0; mt < 2; ++mt)
                #pragma unroll
                for (int ng = 0; ng < 2; ++ng) {
                    mma16816(acc[mt][2 * ng],     ah[mt], &bh[ng][0]);
                    mma16816(acc[mt][2 * ng + 1], ah[mt], &bh[ng][2]);
                }
        }
    }
    __syncthreads();   // everyone done reading X before H overwrites it

    // epilogue 1: bias + gelu (+ split for g-net), H -> XH region
    #pragma unroll
    for (int mt = 0; mt < 2; ++mt)
        #pragma unroll
        for (int nt = 0; nt < 4; ++nt) {
            int r = wm + mt * 16 + tq;
            int c = wn + nt * 8 + tr;
            float v0 = gelu_exact(acc[mt][nt][0] + b1s[c]);
            float v1 = gelu_exact(acc[mt][nt][1] + b1s[c + 1]);
            float v2 = gelu_exact(acc[mt][nt][2] + b1s[c]);
            float v3 = gelu_exact(acc[mt][nt][3] + b1s[c + 1]);
            int c16 = c >> 3, cb = (c & 7) * 2;
            u32 d0 = sw_addr(sbase + SM_XHHI, r, c16) - sbase + cb;
            u32 d8 = sw_addr(sbase + SM_XHHI, r + 8, c16) - sbase + cb;
            if (m == 0) {
                unsigned short h0, l0, h1, l1, h2, l2, h3, l3;
                bf_split(v0, h0, l0); bf_split(v1, h1, l1);
                bf_split(v2, h2, l2); bf_split(v3, h3, l3);
                *(u32*)(smc + d0) = (u32)h0 | ((u32)h1 << 16);
                *(u32*)(smc + d8) = (u32)h2 | ((u32)h3 << 16);
                *(u32*)(smc + d0 + (SM_XHLO - SM_XHHI)) = (u32)l0 | ((u32)l1 << 16);
                *(u32*)(smc + d8 + (SM_XHLO - SM_XHHI)) = (u32)l2 | ((u32)l3 << 16);
            } else {
                *(u32*)(smc + d0) = pack_bf16x2(v0, v1);
                *(u32*)(smc + d8) = pack_bf16x2(v2, v3);
            }
        }

    // m==0: restage gW2^T over the consumed W1 region
    if (m == 0) {
        const uint4* s2h = (const uint4*)g_B2ghi;
        const uint4* s2l = (const uint4*)g_B2glo;
        #pragma unroll
        for (int p = 0; p < 4; ++p) {
            int q = tid + p * 512;
            int r = q >> 4, c16 = q & 15;
            u32 d = (u32)(((r << 4) + (c16 ^ (r & 7))) << 4);
            *(uint4*)(smc + SM_W1HI + d) = s2h[q];
            *(uint4*)(smc + SM_W1LO + d) = s2l[q];
        }
    }
    __syncthreads();

    // ================= Layer 2 =============================================
    if (m == 0) {
        float ac2[2][4][4];
        #pragma unroll
        for (int i = 0; i < 2; ++i)
            #pragma unroll
            for (int j = 0; j < 4; ++j)
                #pragma unroll
                for (int q = 0; q < 4; ++q) ac2[i][j][q] = 0.0f;
        #pragma unroll
        for (int k = 0; k < 8; ++k) {
            const int kc = k * 2;
            u32 ah[2][4], al[2][4], bh[2][4], bl[2][4];
            #pragma unroll
            for (int mt = 0; mt < 2; ++mt) {
                int r = wm + mt * 16 + a_ro;
                ldsm4(ah[mt], sw_addr(sbase + SM_XHHI, r, kc + a_co));
                ldsm4(al[mt], sw_addr(sbase + SM_XHLO, r, kc + a_co));
            }
            #pragma unroll
            for (int ng = 0; ng < 2; ++ng) {
                int r = wn + ng * 16 + b_ro;
                ldsm4(bh[ng], sw_addr(sbase + SM_W1HI, r, kc + b_co));
                ldsm4(bl[ng], sw_addr(sbase + SM_W1LO, r, kc + b_co));
            }
            #pragma unroll
            for (int mt = 0; mt < 2; ++mt)
                #pragma unroll
                for (int ng = 0; ng < 2; ++ng) {
                    mma16816(ac2[mt][2 * ng],     ah[mt], &bh[ng][0]);
                    mma16816(ac2[mt][2 * ng + 1], ah[mt], &bh[ng][2]);
                    mma16816(ac2[mt][2 * ng],     ah[mt], &bl[ng][0]);
                    mma16816(ac2[mt][2 * ng + 1], ah[mt], &bl[ng][2]);
                    mma16816(ac2[mt][2 * ng],     al[mt], &bh[ng][0]);
                    mma16816(ac2[mt][2 * ng + 1], al[mt], &bh[ng][2]);
                }
        }
        #pragma unroll
        for (int mt = 0; mt < 2; ++mt)
            #pragma unroll
            for (int nt = 0; nt < 4; ++nt) {
                int r = wm + mt * 16 + tq;
                int c = wn + nt * 8 + tr;
                float2 o0 = make_float2(ac2[mt][nt][0] + b2s[c],
                                        ac2[mt][nt][1] + b2s[c + 1]);
                float2 o1 = make_float2(ac2[mt][nt][2] + b2s[c],
                                        ac2[mt][nt][3] + b2s[c + 1]);
                *(float2*)(g_Vres + (size_t)(row0 + r) * 128 + c) = o0;
                *(float2*)(g_Vres + (size_t)(row0 + r + 8) * 128 + c) = o1;
                // bf16 residual mirror (= scan step-0 input AND intermediate res)
                *(u32*)((__nv_bfloat16*)g_VresBf + (size_t)(row0 + r) * 128 + c) =
                    pack_bf16x2(o0.x, o0.y);
                *(u32*)((__nv_bfloat16*)g_VresBf + (size_t)(row0 + r + 8) * 128 + c) =
                    pack_bf16x2(o1.x, o1.y);
            }
    } else if (wid < 8) {
        const int wm2 = wid * 16;
        float ac2[2][4];
        #pragma unroll
        for (int j = 0; j < 2; ++j)
            #pragma unroll
            for (int q = 0; q < 4; ++q) ac2[j][q] = 0.0f;
        #pragma unroll
        for (int k = 0; k < 8; ++k) {
            const int kc = k * 2;
            u32 ah[4], bh[4];
            ldsm4(ah, sw_addr(sbase + SM_XHHI, wm2 + a_ro, kc + a_co));
            ldsm4(bh, sw_addr(sbase + SM_F2HI, b_ro, kc + b_co));
            mma16816(ac2[0], ah, &bh[0]);
            mma16816(ac2[1], ah, &bh[2]);
        }
        float* op = g_Wall + (size_t)(m - 1) * R_TOT * K_LNK
                           + (size_t)row0 * K_LNK;
        #pragma unroll
        for (int nt = 0; nt < 2; ++nt) {
            int c = nt * 8 + tr;
            int r = wm2 + tq;
            if (c < 13) {
                op[(r) * K_LNK + c]     = ac2[nt][0] + b2s[c];
                op[(r + 8) * K_LNK + c] = ac2[nt][2] + b2s[c];
            }
            if (c + 1 < 13) {
                op[(r) * K_LNK + c + 1]     = ac2[nt][1] + b2s[c + 1];
                op[(r + 8) * K_LNK + c + 1] = ac2[nt][3] + b2s[c + 1];
            }
        }
    }
}

// ---------------------------------------------------------------------------
// k_scan: chord-mix step, TWO rows per warp, full-MLP gather.
// Phase 1: broadcast all 13 (w, idx); Phase 2: issue ALL 13 LDG.128 into a
// register array (MLP=13, needs high reg budget -> launch_bounds(256, 2));
// Phase 3: accumulate in bf16x2. Residual: bf16 (intermediate) / fp32 (final).
// ---------------------------------------------------------------------------
__global__ void __launch_bounds__(256, 2) k_scan(int m, const int* __restrict__ cols,
                                                 float* __restrict__ out_final) {
    const __nv_bfloat16* Vin = (m == 0) ? g_VresBf
                                        : ((m & 1) ? g_Vbf1 : g_Vbf0);
    __nv_bfloat16* Vout = ((m + 1) & 1) ? g_Vbf1 : g_Vbf0;
    const float* Wm = g_Wall + (size_t)m * R_TOT * K_LNK;

    const int lane = threadIdx.x & 31;
    const int pair = (blockIdx.x * blockDim.x + threadIdx.x) >> 5;
    const int hl   = lane & 15;
    const int lr   = pair * 2 + (lane >> 4);    // this half-warp's row

    u32 wv = 0; int iv = 0;
    if (hl < K_LNK) {
        float w = Wm[lr * K_LNK + hl];
        wv = pack_bf16x2(w, w);
        int s = lr & (S_LEN - 1), b = lr >> 12;
        iv = ((b << 12) | cols[s * K_LNK + hl]) << 4;   // uint4 row base (16/row)
    }

    const int selk = lane & 16;
    u32 wk[K_LNK]; int ik[K_LNK];
    #pragma unroll
    for (int k = 0; k < K_LNK; ++k) {
        wk[k] = __shfl_sync(0xffffffffu, wv, k | selk);
        ik[k] = __shfl_sync(0xffffffffu, iv, k | selk);
    }

    // issue all gathers back-to-back (MLP = 13)
    const uint4* Vin4 = (const uint4*)Vin;
    uint4 v[K_LNK];
    #pragma unroll
    for (int k = 0; k < K_LNK; ++k) v[k] = Vin4[ik[k] + hl];

    u32 a0 = 0, a1 = 0, a2 = 0, a3 = 0;        // bf16x2 mix accumulators
    #pragma unroll
    for (int k = 0; k < K_LNK; ++k) {
        fma_bf2(a0, v[k].x, wk[k]);
        fma_bf2(a1, v[k].y, wk[k]);
        fma_bf2(a2, v[k].z, wk[k]);
        fma_bf2(a3, v[k].w, wk[k]);
    }

    if (m == M_NET - 1) {
        // exact fp32 residual for the final output
        const float4* res4 = (const float4*)g_Vres + ((size_t)lr << 5);
        float4 r0 = res4[hl * 2], r1 = res4[hl * 2 + 1];
        r0.x += __uint_as_float(a0 << 16);
        r0.y += __uint_as_float(a0 & 0xFFFF0000u);
        r0.z += __uint_as_float(a1 << 16);
        r0.w += __uint_as_float(a1 & 0xFFFF0000u);
        r1.x += __uint_as_float(a2 << 16);
        r1.y += __uint_as_float(a2 & 0xFFFF0000u);
        r1.z += __uint_as_float(a3 << 16);
        r1.w += __uint_as_float(a3 & 0xFFFF0000u);
        float4* op = (float4*)out_final + ((size_t)lr << 5);
        op[hl * 2]     = r0;
        op[hl * 2 + 1] = r1;
    } else {
        // bf16 residual: output is bf16-rounded anyway
        uint4 r = ((const uint4*)g_VresBf)[((size_t)lr << 4) + hl];
        uint4 o;
        o.x = add_bf2(r.x, a0);
        o.y = add_bf2(r.y, a1);
        o.z = add_bf2(r.z, a2);
        o.w = add_bf2(r.w, a3);
        ((uint4*)Vout)[((size_t)lr << 4) + hl] = o;
    }
}

// ---------------------------------------------------------------------------
extern "C" void kernel_launch(void* const* d_in, const int* in_sizes, int n_in,
                              void* d_out, int out_size) {
    const int*   data = (const int*)  d_in[0];
    const int*   cols = (const int*)  d_in[1];
    const float* emb  = (const float*)d_in[2];
    const float* apc  = (const float*)d_in[3];
    const float* gW1  = (const float*)d_in[4];
    const float* gb1  = (const float*)d_in[5];
    const float* gW2  = (const float*)d_in[6];
    const float* gb2  = (const float*)d_in[7];
    const float* fW1  = (const float*)d_in[8];
    const float* fb1  = (const float*)d_in[9];
    const float* fW2  = (const float*)d_in[10];
    const float* fb2  = (const float*)d_in[11];
    float* out = (float*)d_out;

    cudaFuncSetAttribute(k_mlp, cudaFuncAttributeMaxDynamicSharedMemorySize,
                         SMEM_MLP);

    // 1) weight prep (transpose + bf16 split)
    k_prep<<<(PREP_TOT + 255) / 256, 256>>>(gW1, gW2, fW1, fW2);

    // 2) embeddings -> bf16 hi/lo
    k_embed<<<(R_TOT * 16) / 256, 256>>>(data, emb, apc);

    // 3) all 13 fused MLPs on warp tensor cores
    dim3 grid_mlp(R_TOT / 128, 13);
    k_mlp<<<grid_mlp, 512, SMEM_MLP>>>(gb1, gb2, fb1, fb2);

    // 4) 12 chord-mix scan steps (2 rows/warp, full-MLP bf16 gathers)
    for (int m = 0; m < M_NET; ++m)
        k_scan<<<R_TOT / 16, 256>>>(m, cols, out);
}

// round 13
// speedup vs baseline: 1.0002x; 1.0002x over previous
#include <cuda_runtime.h>
#include <cuda_bf16.h>
#include <math.h>
#include <stdint.h>

#define R_TOT 16384
#define S_LEN 4096
#define D_DIM 128
#define K_LNK 13
#define M_NET 12
#define NBLK  512        // k_scan_all grid size (must all be co-resident)

typedef unsigned int u32;
typedef unsigned long long u64;

// ---------------- scratch (static device memory only) ----------------------
__device__ __nv_bfloat16 g_Xhi[R_TOT * D_DIM];          // X hi, row-major
__device__ __nv_bfloat16 g_Xlo[R_TOT * D_DIM];          // X lo
__device__ __nv_bfloat16 g_B1hi[13 * 128 * 128];        // W1^T [net][n][k]
__device__ __nv_bfloat16 g_B1lo[13 * 128 * 128];
__device__ __nv_bfloat16 g_B2ghi[128 * 128];            // gW2^T [n][k]
__device__ __nv_bfloat16 g_B2glo[128 * 128];
__device__ __nv_bfloat16 g_B2fhi[12 * 16 * 128];        // fW2^T padded N=16
__device__ float g_Vres[R_TOT * D_DIM];                 // fp32 residual (exact)
__device__ __nv_bfloat16 g_VresBf[R_TOT * D_DIM];       // bf16 residual mirror
__device__ __nv_bfloat16 g_Vbf0[R_TOT * D_DIM];         // bf16 V ping
__device__ __nv_bfloat16 g_Vbf1[R_TOT * D_DIM];         // bf16 V pong
__device__ float g_Wall[M_NET * R_TOT * K_LNK];
__device__ int g_bar;                                   // persistent-scan barrier

// ---------------- helpers ---------------------------------------------------
__device__ __forceinline__ u32 smem_u32(const void* p) {
    u32 a;
    asm("{ .reg .u64 t; cvta.to.shared.u64 t, %1; cvt.u32.u64 %0, t; }"
        : "=r"(a) : "l"(p));
    return a;
}
__device__ __forceinline__ void ldsm4(u32* r, u32 addr) {
    asm volatile("ldmatrix.sync.aligned.m8n8.x4.shared.b16 {%0,%1,%2,%3}, [%4];"
        : "=r"(r[0]), "=r"(r[1]), "=r"(r[2]), "=r"(r[3]) : "r"(addr));
}
__device__ __forceinline__ void mma16816(float* d, const u32* a, const u32* b) {
    asm volatile(
        "mma.sync.aligned.m16n8k16.row.col.f32.bf16.bf16.f32 "
        "{%0,%1,%2,%3}, {%4,%5,%6,%7}, {%8,%9}, {%0,%1,%2,%3};"
        : "+f"(d[0]), "+f"(d[1]), "+f"(d[2]), "+f"(d[3])
        : "r"(a[0]), "r"(a[1]), "r"(a[2]), "r"(a[3]), "r"(b[0]), "r"(b[1]));
}
// swizzled byte address of 16B unit (r, c16) in a [rows][128]bf16 smem tile
__device__ __forceinline__ u32 sw_addr(u32 base, int r, int c16) {
    return base + (u32)(((r << 4) + (c16 ^ (r & 7))) << 4);
}
__device__ __forceinline__ void bf_split(float v, unsigned short& h,
                                         unsigned short& l) {
    __nv_bfloat16 hb = __float2bfloat16(v);
    __nv_bfloat16 lb = __float2bfloat16(v - __bfloat162float(hb));
    h = __bfloat16_as_ushort(hb);
    l = __bfloat16_as_ushort(lb);
}
// pack two fp32 -> bf16x2 (lo arg in low half = memory-first element)
__device__ __forceinline__ u32 pack_bf16x2(float lo, float hi) {
    u32 r;
    asm("cvt.rn.bf16x2.f32 %0, %1, %2;" : "=r"(r) : "f"(hi), "f"(lo));
    return r;
}
__device__ __forceinline__ void fma_bf2(u32& d, u32 a, u32 b) {
    asm("fma.rn.bf16x2 %0, %1, %2, %0;" : "+r"(d) : "r"(a), "r"(b));
}
__device__ __forceinline__ u32 add_bf2(u32 a, u32 b) {
    u32 r;
    asm("add.rn.bf16x2 %0, %1, %2;" : "=r"(r) : "r"(a), "r"(b));
    return r;
}
__device__ __forceinline__ float gelu_exact(float x) {
    return 0.5f * x * (1.0f + erff(x * 0.70710678118654752440f));
}

// ---------------------------------------------------------------------------
// Fused init: weight prep (transpose + bf16 split) + embeddings.
// PREP_TOT = 126976 = 496 blocks exactly -> clean block-granular split.
// ---------------------------------------------------------------------------
#define PREP_A (13 * 128 * 64)
#define PREP_B (128 * 64)
#define PREP_C (12 * 16 * 64)
#define PREP_TOT (PREP_A + PREP_B + PREP_C)
#define EMB_TOT (R_TOT * 16)
#define INIT_TOT (PREP_TOT + EMB_TOT)

__global__ void k_init(const float* __restrict__ gW1,
                       const float* __restrict__ gW2,
                       const float* __restrict__ fW1,
                       const float* __restrict__ fW2,
                       const int* __restrict__ data,
                       const float* __restrict__ emb,
                       const float* __restrict__ apc) {
    int t = blockIdx.x * blockDim.x + threadIdx.x;
    if (t < PREP_TOT) {
        float w0, w1;
        if (t < PREP_A) {
            int net = t >> 13;
            int r = t & 8191;
            int n = r >> 6, k = (r & 63) * 2;
            const float* W1 = (net == 0) ? gW1
                                         : fW1 + (size_t)(net - 1) * 128 * 128;
            w0 = W1[k * 128 + n];
            w1 = W1[(k + 1) * 128 + n];
            int widx = (net * 128 + n) * 64 + (k >> 1);
            unsigned short h0, l0, h1, l1;
            bf_split(w0, h0, l0); bf_split(w1, h1, l1);
            ((u32*)g_B1hi)[widx] = (u32)h0 | ((u32)h1 << 16);
            ((u32*)g_B1lo)[widx] = (u32)l0 | ((u32)l1 << 16);
        } else if (t < PREP_A + PREP_B) {
            int r = t - PREP_A;
            int n = r >> 6, k = (r & 63) * 2;
            w0 = gW2[k * 128 + n];
            w1 = gW2[(k + 1) * 128 + n];
            int widx = n * 64 + (k >> 1);
            unsigned short h0, l0, h1, l1;
            bf_split(w0, h0, l0); bf_split(w1, h1, l1);
            ((u32*)g_B2ghi)[widx] = (u32)h0 | ((u32)h1 << 16);
            ((u32*)g_B2glo)[widx] = (u32)l0 | ((u32)l1 << 16);
        } else {
            int r = t - PREP_A - PREP_B;
            int net = r >> 10;
            int rr = r & 1023;
            int n = rr >> 6, k = (rr & 63) * 2;
            w0 = (n < 13) ? fW2[(size_t)net * 128 * 13 + k * 13 + n] : 0.0f;
            w1 = (n < 13) ? fW2[(size_t)net * 128 * 13 + (k + 1) * 13 + n] : 0.0f;
            ((u32*)g_B2fhi)[(net * 16 + n) * 64 + (k >> 1)] =
                pack_bf16x2(w0, w1);
        }
    } else {
        int idx = t - PREP_TOT;
        if (idx >= EMB_TOT) return;
        int row = idx >> 4;
        int g8 = idx & 15;
        int tok = data[row];
        int s = row & (S_LEN - 1);
        float4 e0 = ((const float4*)emb)[tok * 32 + g8 * 2];
        float4 e1 = ((const float4*)emb)[tok * 32 + g8 * 2 + 1];
        float4 a0 = ((const float4*)apc)[s * 32 + g8 * 2];
        float4 a1 = ((const float4*)apc)[s * 32 + g8 * 2 + 1];
        float v[8] = {e0.x + a0.x, e0.y + a0.y, e0.z + a0.z, e0.w + a0.w,
                      e1.x + a1.x, e1.y + a1.y, e1.z + a1.z, e1.w + a1.w};
        u32 hp[4], lp[4];
        #pragma unroll
        for (int p = 0; p < 4; ++p) {
            unsigned short h0, l0, h1, l1;
            bf_split(v[2 * p], h0, l0);
            bf_split(v[2 * p + 1], h1, l1);
            hp[p] = (u32)h0 | ((u32)h1 << 16);
            lp[p] = (u32)l0 | ((u32)l1 << 16);
        }
        ((uint4*)g_Xhi)[row * 16 + g8] = make_uint4(hp[0], hp[1], hp[2], hp[3]);
        ((uint4*)g_Xlo)[row * 16 + g8] = make_uint4(lp[0], lp[1], lp[2], lp[3]);
    }
}

// ---------------------------------------------------------------------------
// k_mlp: warp-MMA fused 2-layer MLP (unchanged from R11 — proven).
// ---------------------------------------------------------------------------
#define SM_W1HI  0
#define SM_W1LO  32768
#define SM_XHHI  65536
#define SM_XHLO  98304
#define SM_F2HI  131072
#define SM_B1S   139264
#define SM_B2S   139776
#define SMEM_MLP 140288

extern __shared__ char smc[];

__global__ void __launch_bounds__(512, 1) k_mlp(
    const float* __restrict__ gb1, const float* __restrict__ gb2,
    const float* __restrict__ fb1, const float* __restrict__ fb2) {
    const int tid = threadIdx.x;
    const int lane = tid & 31;
    const int wid = tid >> 5;
    const int m = blockIdx.y;
    const int row0 = blockIdx.x * 128;
    const u32 sbase = smem_u32(smc);
    float* b1s = (float*)(smc + SM_B1S);
    float* b2s = (float*)(smc + SM_B2S);

    // ---- stage into swizzled smem (lo regions only for g-net) ----
    {
        const uint4* s1h = (const uint4*)g_B1hi + m * 2048;
        const uint4* s1l = (const uint4*)g_B1lo + m * 2048;
        const uint4* sxh = (const uint4*)g_Xhi + row0 * 16;
        const uint4* sxl = (const uint4*)g_Xlo + row0 * 16;
        #pragma unroll
        for (int p = 0; p < 4; ++p) {
            int q = tid + p * 512;
            int r = q >> 4, c16 = q & 15;
            u32 d = (u32)(((r << 4) + (c16 ^ (r & 7))) << 4);
            *(uint4*)(smc + SM_W1HI + d) = s1h[q];
            *(uint4*)(smc + SM_XHHI + d) = sxh[q];
            if (m == 0) {
                *(uint4*)(smc + SM_W1LO + d) = s1l[q];
                *(uint4*)(smc + SM_XHLO + d) = sxl[q];
            }
        }
    }
    if (m > 0) {
        const uint4* sfh = (const uint4*)g_B2fhi + (m - 1) * 256;
        if (tid < 256) {
            int r = tid >> 4, c16 = tid & 15;
            u32 d = (u32)(((r << 4) + (c16 ^ (r & 7))) << 4);
            *(uint4*)(smc + SM_F2HI + d) = sfh[tid];
        }
        if (tid < 128) b1s[tid] = fb1[(m - 1) * 128 + tid];
        if (tid < 16)  b2s[tid] = (tid < 13) ? fb2[(m - 1) * 13 + tid] : 0.0f;
    } else {
        if (tid < 128) { b1s[tid] = gb1[tid]; b2s[tid] = gb2[tid]; }
    }
    __syncthreads();

    // fragment lane offsets
    const int a_ro = (lane & 7) + (lane & 8);
    const int a_co = lane >> 4;
    const int b_ro = (lane & 7) + ((lane >> 1) & 8);
    const int b_co = (lane >> 3) & 1;
    const int tq = lane >> 2;
    const int tr = (lane & 3) * 2;

    const int wm = (wid & 3) * 32;    // warp M offset
    const int wn = (wid >> 2) * 32;   // warp N offset

    // ================= Layer 1: H = gelu(X @ W1 + b1) ======================
    float acc[2][4][4];
    #pragma unroll
    for (int i = 0; i < 2; ++i)
        #pragma unroll
        for (int j = 0; j < 4; ++j)
            #pragma unroll
            for (int q = 0; q < 4; ++q) acc[i][j][q] = 0.0f;

    if (m == 0) {
        #pragma unroll
        for (int k = 0; k < 8; ++k) {
            const int kc = k * 2;
            u32 ah[2][4], al[2][4], bh[2][4], bl[2][4];
            #pragma unroll
            for (int mt = 0; mt < 2; ++mt) {
                int r = wm + mt * 16 + a_ro;
                ldsm4(ah[mt], sw_addr(sbase + SM_XHHI, r, kc + a_co));
                ldsm4(al[mt], sw_addr(sbase + SM_XHLO, r, kc + a_co));
            }
            #pragma unroll
            for (int ng = 0; ng < 2; ++ng) {
                int r = wn + ng * 16 + b_ro;
                ldsm4(bh[ng], sw_addr(sbase + SM_W1HI, r, kc + b_co));
                ldsm4(bl[ng], sw_addr(sbase + SM_W1LO, r, kc + b_co));
            }
            #pragma unroll
            for (int mt = 0; mt < 2; ++mt)
                #pragma unroll
                for (int ng = 0; ng < 2; ++ng) {
                    mma16816(acc[mt][2 * ng],     ah[mt], &bh[ng][0]);
                    mma16816(acc[mt][2 * ng + 1], ah[mt], &bh[ng][2]);
                    mma16816(acc[mt][2 * ng],     ah[mt], &bl[ng][0]);
                    mma16816(acc[mt][2 * ng + 1], ah[mt], &bl[ng][2]);
                    mma16816(acc[mt][2 * ng],     al[mt], &bh[ng][0]);
                    mma16816(acc[mt][2 * ng + 1], al[mt], &bh[ng][2]);
                }
        }
    } else {
        #pragma unroll
        for (int k = 0; k < 8; ++k) {
            const int kc = k * 2;
            u32 ah[2][4], bh[2][4];
            #pragma unroll
            for (int mt = 0; mt < 2; ++mt)
                ldsm4(ah[mt], sw_addr(sbase + SM_XHHI, wm + mt * 16 + a_ro, kc + a_co));
            #pragma unroll
            for (int ng = 0; ng < 2; ++ng)
                ldsm4(bh[ng], sw_addr(sbase + SM_W1HI, wn + ng * 16 + b_ro, kc + b_co));
            #pragma unroll
            for (int mt = 0; mt < 2; ++mt)
                #pragma unroll
                for (int ng = 0; ng < 2; ++ng) {
                    mma16816(acc[mt][2 * ng],     ah[mt], &bh[ng][0]);
                    mma16816(acc[mt][2 * ng + 1], ah[mt], &bh[ng][2]);
                }
        }
    }
    __syncthreads();   // everyone done reading X before H overwrites it

    // epilogue 1: bias + gelu (+ split for g-net), H -> XH region
    #pragma unroll
    for (int mt = 0; mt < 2; ++mt)
        #pragma unroll
        for (int nt = 0; nt < 4; ++nt) {
            int r = wm + mt * 16 + tq;
            int c = wn + nt * 8 + tr;
            float v0 = gelu_exact(acc[mt][nt][0] + b1s[c]);
            float v1 = gelu_exact(acc[mt][nt][1] + b1s[c + 1]);
            float v2 = gelu_exact(acc[mt][nt][2] + b1s[c]);
            float v3 = gelu_exact(acc[mt][nt][3] + b1s[c + 1]);
            int c16 = c >> 3, cb = (c & 7) * 2;
            u32 d0 = sw_addr(sbase + SM_XHHI, r, c16) - sbase + cb;
            u32 d8 = sw_addr(sbase + SM_XHHI, r + 8, c16) - sbase + cb;
            if (m == 0) {
                unsigned short h0, l0, h1, l1, h2, l2, h3, l3;
                bf_split(v0, h0, l0); bf_split(v1, h1, l1);
                bf_split(v2, h2, l2); bf_split(v3, h3, l3);
                *(u32*)(smc + d0) = (u32)h0 | ((u32)h1 << 16);
                *(u32*)(smc + d8) = (u32)h2 | ((u32)h3 << 16);
                *(u32*)(smc + d0 + (SM_XHLO - SM_XHHI)) = (u32)l0 | ((u32)l1 << 16);
                *(u32*)(smc + d8 + (SM_XHLO - SM_XHHI)) = (u32)l2 | ((u32)l3 << 16);
            } else {
                *(u32*)(smc + d0) = pack_bf16x2(v0, v1);
                *(u32*)(smc + d8) = pack_bf16x2(v2, v3);
            }
        }

    // m==0: restage gW2^T over the consumed W1 region
    if (m == 0) {
        const uint4* s2h = (const uint4*)g_B2ghi;
        const uint4* s2l = (const uint4*)g_B2glo;
        #pragma unroll
        for (int p = 0; p < 4; ++p) {
            int q = tid + p * 512;
            int r = q >> 4, c16 = q & 15;
            u32 d = (u32)(((r << 4) + (c16 ^ (r & 7))) << 4);
            *(uint4*)(smc + SM_W1HI + d) = s2h[q];
            *(uint4*)(smc + SM_W1LO + d) = s2l[q];
        }
    }
    __syncthreads();

    // ================= Layer 2 =============================================
    if (m == 0) {
        float ac2[2][4][4];
        #pragma unroll
        for (int i = 0; i < 2; ++i)
            #pragma unroll
            for (int j = 0; j < 4; ++j)
                #pragma unroll
                for (int q = 0; q < 4; ++q) ac2[i][j][q] = 0.0f;
        #pragma unroll
        for (int k = 0; k < 8; ++k) {
            const int kc = k * 2;
            u32 ah[2][4], al[2][4], bh[2][4], bl[2][4];
            #pragma unroll
            for (int mt = 0; mt < 2; ++mt) {
                int r = wm + mt * 16 + a_ro;
                ldsm4(ah[mt], sw_addr(sbase + SM_XHHI, r, kc + a_co));
                ldsm4(al[mt], sw_addr(sbase + SM_XHLO, r, kc + a_co));
            }
            #pragma unroll
            for (int ng = 0; ng < 2; ++ng) {
                int r = wn + ng * 16 + b_ro;
                ldsm4(bh[ng], sw_addr(sbase + SM_W1HI, r, kc + b_co));
                ldsm4(bl[ng], sw_addr(sbase + SM_W1LO, r, kc + b_co));
            }
            #pragma unroll
            for (int mt = 0; mt < 2; ++mt)
                #pragma unroll
                for (int ng = 0; ng < 2; ++ng) {
                    mma16816(ac2[mt][2 * ng],     ah[mt], &bh[ng][0]);
                    mma16816(ac2[mt][2 * ng + 1], ah[mt], &bh[ng][2]);
                    mma16816(ac2[mt][2 * ng],     ah[mt], &bl[ng][0]);
                    mma16816(ac2[mt][2 * ng + 1], ah[mt], &bl[ng][2]);
                    mma16816(ac2[mt][2 * ng],     al[mt], &bh[ng][0]);
                    mma16816(ac2[mt][2 * ng + 1], al[mt], &bh[ng][2]);
                }
        }
        #pragma unroll
        for (int mt = 0; mt < 2; ++mt)
            #pragma unroll
            for (int nt = 0; nt < 4; ++nt) {
                int r = wm + mt * 16 + tq;
                int c = wn + nt * 8 + tr;
                float2 o0 = make_float2(ac2[mt][nt][0] + b2s[c],
                                        ac2[mt][nt][1] + b2s[c + 1]);
                float2 o1 = make_float2(ac2[mt][nt][2] + b2s[c],
                                        ac2[mt][nt][3] + b2s[c + 1]);
                *(float2*)(g_Vres + (size_t)(row0 + r) * 128 + c) = o0;
                *(float2*)(g_Vres + (size_t)(row0 + r + 8) * 128 + c) = o1;
                *(u32*)((__nv_bfloat16*)g_VresBf + (size_t)(row0 + r) * 128 + c) =
                    pack_bf16x2(o0.x, o0.y);
                *(u32*)((__nv_bfloat16*)g_VresBf + (size_t)(row0 + r + 8) * 128 + c) =
                    pack_bf16x2(o1.x, o1.y);
            }
    } else if (wid < 8) {
        const int wm2 = wid * 16;
        float ac2[2][4];
        #pragma unroll
        for (int j = 0; j < 2; ++j)
            #pragma unroll
            for (int q = 0; q < 4; ++q) ac2[j][q] = 0.0f;
        #pragma unroll
        for (int k = 0; k < 8; ++k) {
            const int kc = k * 2;
            u32 ah[4], bh[4];
            ldsm4(ah, sw_addr(sbase + SM_XHHI, wm2 + a_ro, kc + a_co));
            ldsm4(bh, sw_addr(sbase + SM_F2HI, b_ro, kc + b_co));
            mma16816(ac2[0], ah, &bh[0]);
            mma16816(ac2[1], ah, &bh[2]);
        }
        float* op = g_Wall + (size_t)(m - 1) * R_TOT * K_LNK
                           + (size_t)row0 * K_LNK;
        #pragma unroll
        for (int nt = 0; nt < 2; ++nt) {
            int c = nt * 8 + tr;
            int r = wm2 + tq;
            if (c < 13) {
                op[(r) * K_LNK + c]     = ac2[nt][0] + b2s[c];
                op[(r + 8) * K_LNK + c] = ac2[nt][2] + b2s[c];
            }
            if (c + 1 < 13) {
                op[(r) * K_LNK + c + 1]     = ac2[nt][1] + b2s[c + 1];
                op[(r + 8) * K_LNK + c + 1] = ac2[nt][3] + b2s[c + 1];
            }
        }
    }
}

// ---------------------------------------------------------------------------
// k_scan_all: ALL 12 chord-mix steps in one persistent kernel.
// 512 blocks x 256 thr; block owns 32 rows (8 warps x 2 rows x 2 iters).
// Per-step body = R11 scan (2 rows/warp, bf16x2 mix, shfl broadcast).
// cols-derived indices + bf16 residual live in REGISTERS across all steps.
// Inter-step sync: monotonic global barrier (all blocks co-resident:
// launch_bounds(256,4) => <=64 regs => capacity 4/SM * 148 = 592 >= 512).
// V gathers use __ldcg (L2-coherent; L1 is stale across in-kernel barriers).
// Counter self-resets on the last arrival -> deterministic across replays.
// ---------------------------------------------------------------------------
__global__ void __launch_bounds__(256, 4) k_scan_all(
    const int* __restrict__ cols, float* __restrict__ out_final) {
    const int lane = threadIdx.x & 31;
    const int wid  = threadIdx.x >> 5;
    const int hl   = lane & 15;
    const int half = lane >> 4;
    const int selk = lane & 16;
    const int base = blockIdx.x * 32 + wid * 2;   // pair base; +16 for iter 1

    // register-resident per-row state (constant across steps)
    int iv[2];
    uint4 resbf[2];
    #pragma unroll
    for (int t = 0; t < 2; ++t) {
        int lr = base + t * 16 + half;
        if (hl < K_LNK) {
            int s = lr & (S_LEN - 1), b = lr >> 12;
            iv[t] = ((b << 12) | cols[s * K_LNK + hl]) << 4;  // uint4 row base
        } else iv[t] = 0;
        resbf[t] = ((const uint4*)g_VresBf)[((size_t)lr << 4) + hl];
    }

    for (int m = 0; m < M_NET; ++m) {
        const __nv_bfloat16* Vin = (m == 0) ? g_VresBf
                                            : ((m & 1) ? g_Vbf1 : g_Vbf0);
        __nv_bfloat16* Vout = ((m + 1) & 1) ? g_Vbf1 : g_Vbf0;
        const float* Wm = g_Wall + (size_t)m * R_TOT * K_LNK;
        const uint4* Vin4 = (const uint4*)Vin;

        #pragma unroll
        for (int t = 0; t < 2; ++t) {
            int lr = base + t * 16 + half;
            u32 wv = 0;
            if (hl < K_LNK) {
                float w = Wm[lr * K_LNK + hl];
                wv = pack_bf16x2(w, w);
            }
            u32 a0 = 0, a1 = 0, a2 = 0, a3 = 0;
            #pragma unroll
            for (int k = 0; k < K_LNK; ++k) {
                u32 wk = __shfl_sync(0xffffffffu, wv, k | selk);
                int ik = __shfl_sync(0xffffffffu, iv[t], k | selk);
                uint4 v = __ldcg(Vin4 + ik + hl);
                fma_bf2(a0, v.x, wk);
                fma_bf2(a1, v.y, wk);
                fma_bf2(a2, v.z, wk);
                fma_bf2(a3, v.w, wk);
            }
            if (m == M_NET - 1) {
                const float4* res4 = (const float4*)g_Vres + ((size_t)lr << 5);
                float4 r0 = res4[hl * 2], r1 = res4[hl * 2 + 1];
                r0.x += __uint_as_float(a0 << 16);
                r0.y += __uint_as_float(a0 & 0xFFFF0000u);
                r0.z += __uint_as_float(a1 << 16);
                r0.w += __uint_as_float(a1 & 0xFFFF0000u);
                r1.x += __uint_as_float(a2 << 16);
                r1.y += __uint_as_float(a2 & 0xFFFF0000u);
                r1.z += __uint_as_float(a3 << 16);
                r1.w += __uint_as_float(a3 & 0xFFFF0000u);
                float4* op = (float4*)out_final + ((size_t)lr << 5);
                op[hl * 2]     = r0;
                op[hl * 2 + 1] = r1;
            } else {
                uint4 o;
                o.x = add_bf2(resbf[t].x, a0);
                o.y = add_bf2(resbf[t].y, a1);
                o.z = add_bf2(resbf[t].z, a2);
                o.w = add_bf2(resbf[t].w, a3);
                ((uint4*)Vout)[((size_t)lr << 4) + hl] = o;
            }
        }

        if (m < M_NET - 1) {
            // grid barrier: monotonic counter, threshold (m+1)*NBLK
            __syncthreads();
            if (threadIdx.x == 0) {
                __threadfence();
                atomicAdd(&g_bar, 1);
                int target = (m + 1) * NBLK;
                while (*(volatile int*)&g_bar < target) __nanosleep(64);
            }
            __syncthreads();
        }
    }

    // final arrival set: last block resets the counter for the next replay
    __syncthreads();
    if (threadIdx.x == 0) {
        __threadfence();
        int old = atomicAdd(&g_bar, 1);
        if (old == M_NET * NBLK - 1)
            *(volatile int*)&g_bar = 0;
    }
}

// ---------------------------------------------------------------------------
extern "C" void kernel_launch(void* const* d_in, const int* in_sizes, int n_in,
                              void* d_out, int out_size) {
    const int*   data = (const int*)  d_in[0];
    const int*   cols = (const int*)  d_in[1];
    const float* emb  = (const float*)d_in[2];
    const float* apc  = (const float*)d_in[3];
    const float* gW1  = (const float*)d_in[4];
    const float* gb1  = (const float*)d_in[5];
    const float* gW2  = (const float*)d_in[6];
    const float* gb2  = (const float*)d_in[7];
    const float* fW1  = (const float*)d_in[8];
    const float* fb1  = (const float*)d_in[9];
    const float* fW2  = (const float*)d_in[10];
    const float* fb2  = (const float*)d_in[11];
    float* out = (float*)d_out;

    cudaFuncSetAttribute(k_mlp, cudaFuncAttributeMaxDynamicSharedMemorySize,
                         SMEM_MLP);

    // 1) fused weight prep + embeddings
    k_init<<<(INIT_TOT + 255) / 256, 256>>>(gW1, gW2, fW1, fW2,
                                            data, emb, apc);

    // 2) all 13 fused MLPs on warp tensor cores
    dim3 grid_mlp(R_TOT / 128, 13);
    k_mlp<<<grid_mlp, 512, SMEM_MLP>>>(gb1, gb2, fb1, fb2);

    // 3) all 12 chord-mix scan steps in one persistent kernel
    k_scan_all<<<NBLK, 256>>>(cols, out);
}

// round 14
// speedup vs baseline: 1.1466x; 1.1463x over previous
#include <cuda_runtime.h>
#include <cuda_bf16.h>
#include <math.h>
#include <stdint.h>

#define R_TOT 16384
#define S_LEN 4096
#define D_DIM 128
#define K_LNK 13
#define M_NET 12

typedef unsigned int u32;
typedef unsigned long long u64;

// ---------------- scratch (static device memory only) ----------------------
__device__ __nv_bfloat16 g_Xhi[R_TOT * D_DIM];          // X hi, row-major
__device__ __nv_bfloat16 g_Xlo[R_TOT * D_DIM];          // X lo
__device__ __nv_bfloat16 g_B1hi[13 * 128 * 128];        // W1^T [net][n][k]
__device__ __nv_bfloat16 g_B1lo[13 * 128 * 128];
__device__ __nv_bfloat16 g_B2ghi[128 * 128];            // gW2^T [n][k]
__device__ __nv_bfloat16 g_B2glo[128 * 128];
__device__ __nv_bfloat16 g_B2fhi[12 * 16 * 128];        // fW2^T padded N=16
__device__ float g_Vres[R_TOT * D_DIM];                 // fp32 residual (exact)
__device__ __nv_bfloat16 g_VresBf[R_TOT * D_DIM];       // bf16 residual mirror
__device__ __nv_bfloat16 g_Vbf0[R_TOT * D_DIM];         // bf16 V ping
__device__ __nv_bfloat16 g_Vbf1[R_TOT * D_DIM];         // bf16 V pong
__device__ float g_Wall[M_NET * R_TOT * K_LNK];

// ---------------- helpers ---------------------------------------------------
__device__ __forceinline__ u32 smem_u32(const void* p) {
    u32 a;
    asm("{ .reg .u64 t; cvta.to.shared.u64 t, %1; cvt.u32.u64 %0, t; }"
        : "=r"(a) : "l"(p));
    return a;
}
__device__ __forceinline__ void ldsm4(u32* r, u32 addr) {
    asm volatile("ldmatrix.sync.aligned.m8n8.x4.shared.b16 {%0,%1,%2,%3}, [%4];"
        : "=r"(r[0]), "=r"(r[1]), "=r"(r[2]), "=r"(r[3]) : "r"(addr));
}
__device__ __forceinline__ void mma16816(float* d, const u32* a, const u32* b) {
    asm volatile(
        "mma.sync.aligned.m16n8k16.row.col.f32.bf16.bf16.f32 "
        "{%0,%1,%2,%3}, {%4,%5,%6,%7}, {%8,%9}, {%0,%1,%2,%3};"
        : "+f"(d[0]), "+f"(d[1]), "+f"(d[2]), "+f"(d[3])
        : "r"(a[0]), "r"(a[1]), "r"(a[2]), "r"(a[3]), "r"(b[0]), "r"(b[1]));
}
// swizzled byte address of 16B unit (r, c16) in a [rows][128]bf16 smem tile
__device__ __forceinline__ u32 sw_addr(u32 base, int r, int c16) {
    return base + (u32)(((r << 4) + (c16 ^ (r & 7))) << 4);
}
__device__ __forceinline__ void bf_split(float v, unsigned short& h,
                                         unsigned short& l) {
    __nv_bfloat16 hb = __float2bfloat16(v);
    __nv_bfloat16 lb = __float2bfloat16(v - __bfloat162float(hb));
    h = __bfloat16_as_ushort(hb);
    l = __bfloat16_as_ushort(lb);
}
// pack two fp32 -> bf16x2 (lo arg in low half = memory-first element)
__device__ __forceinline__ u32 pack_bf16x2(float lo, float hi) {
    u32 r;
    asm("cvt.rn.bf16x2.f32 %0, %1, %2;" : "=r"(r) : "f"(hi), "f"(lo));
    return r;
}
__device__ __forceinline__ void fma_bf2(u32& d, u32 a, u32 b) {
    asm("fma.rn.bf16x2 %0, %1, %2, %0;" : "+r"(d) : "r"(a), "r"(b));
}
__device__ __forceinline__ u32 add_bf2(u32 a, u32 b) {
    u32 r;
    asm("add.rn.bf16x2 %0, %1, %2;" : "=r"(r) : "r"(a), "r"(b));
    return r;
}
__device__ __forceinline__ float gelu_exact(float x) {
    return 0.5f * x * (1.0f + erff(x * 0.70710678118654752440f));
}

// ---------------------------------------------------------------------------
// Fused init: weight prep (transpose + bf16 split) + embeddings.
// ---------------------------------------------------------------------------
#define PREP_A (13 * 128 * 64)
#define PREP_B (128 * 64)
#define PREP_C (12 * 16 * 64)
#define PREP_TOT (PREP_A + PREP_B + PREP_C)
#define EMB_TOT (R_TOT * 16)
#define INIT_TOT (PREP_TOT + EMB_TOT)

__global__ void k_init(const float* __restrict__ gW1,
                       const float* __restrict__ gW2,
                       const float* __restrict__ fW1,
                       const float* __restrict__ fW2,
                       const int* __restrict__ data,
                       const float* __restrict__ emb,
                       const float* __restrict__ apc) {
    int t = blockIdx.x * blockDim.x + threadIdx.x;
    if (t < PREP_TOT) {
        float w0, w1;
        if (t < PREP_A) {
            int net = t >> 13;
            int r = t & 8191;
            int n = r >> 6, k = (r & 63) * 2;
            const float* W1 = (net == 0) ? gW1
                                         : fW1 + (size_t)(net - 1) * 128 * 128;
            w0 = W1[k * 128 + n];
            w1 = W1[(k + 1) * 128 + n];
            int widx = (net * 128 + n) * 64 + (k >> 1);
            unsigned short h0, l0, h1, l1;
            bf_split(w0, h0, l0); bf_split(w1, h1, l1);
            ((u32*)g_B1hi)[widx] = (u32)h0 | ((u32)h1 << 16);
            ((u32*)g_B1lo)[widx] = (u32)l0 | ((u32)l1 << 16);
        } else if (t < PREP_A + PREP_B) {
            int r = t - PREP_A;
            int n = r >> 6, k = (r & 63) * 2;
            w0 = gW2[k * 128 + n];
            w1 = gW2[(k + 1) * 128 + n];
            int widx = n * 64 + (k >> 1);
            unsigned short h0, l0, h1, l1;
            bf_split(w0, h0, l0); bf_split(w1, h1, l1);
            ((u32*)g_B2ghi)[widx] = (u32)h0 | ((u32)h1 << 16);
            ((u32*)g_B2glo)[widx] = (u32)l0 | ((u32)l1 << 16);
        } else {
            int r = t - PREP_A - PREP_B;
            int net = r >> 10;
            int rr = r & 1023;
            int n = rr >> 6, k = (rr & 63) * 2;
            w0 = (n < 13) ? fW2[(size_t)net * 128 * 13 + k * 13 + n] : 0.0f;
            w1 = (n < 13) ? fW2[(size_t)net * 128 * 13 + (k + 1) * 13 + n] : 0.0f;
            ((u32*)g_B2fhi)[(net * 16 + n) * 64 + (k >> 1)] =
                pack_bf16x2(w0, w1);
        }
    } else {
        int idx = t - PREP_TOT;
        if (idx >= EMB_TOT) return;
        int row = idx >> 4;
        int g8 = idx & 15;
        int tok = data[row];
        int s = row & (S_LEN - 1);
        float4 e0 = ((const float4*)emb)[tok * 32 + g8 * 2];
        float4 e1 = ((const float4*)emb)[tok * 32 + g8 * 2 + 1];
        float4 a0 = ((const float4*)apc)[s * 32 + g8 * 2];
        float4 a1 = ((const float4*)apc)[s * 32 + g8 * 2 + 1];
        float v[8] = {e0.x + a0.x, e0.y + a0.y, e0.z + a0.z, e0.w + a0.w,
                      e1.x + a1.x, e1.y + a1.y, e1.z + a1.z, e1.w + a1.w};
        u32 hp[4], lp[4];
        #pragma unroll
        for (int p = 0; p < 4; ++p) {
            unsigned short h0, l0, h1, l1;
            bf_split(v[2 * p], h0, l0);
            bf_split(v[2 * p + 1], h1, l1);
            hp[p] = (u32)h0 | ((u32)h1 << 16);
            lp[p] = (u32)l0 | ((u32)l1 << 16);
        }
        ((uint4*)g_Xhi)[row * 16 + g8] = make_uint4(hp[0], hp[1], hp[2], hp[3]);
        ((uint4*)g_Xlo)[row * 16 + g8] = make_uint4(lp[0], lp[1], lp[2], lp[3]);
    }
}

// ---------------------------------------------------------------------------
// k_mlp_g: g-net only (3-term bf16 hi/lo split, fp32 backbone).
// grid = 128 row-tiles, 512 threads, 140 KB smem (1 CTA/SM).
// ---------------------------------------------------------------------------
#define G_W1HI  0
#define G_W1LO  32768
#define G_XHHI  65536
#define G_XHLO  98304
#define G_B1S   131072
#define G_B2S   131584
#define SMEM_G  132096

extern __shared__ char smc[];

__global__ void __launch_bounds__(512, 1) k_mlp_g(
    const float* __restrict__ gb1, const float* __restrict__ gb2) {
    const int tid = threadIdx.x;
    const int lane = tid & 31;
    const int wid = tid >> 5;
    const int row0 = blockIdx.x * 128;
    const u32 sbase = smem_u32(smc);
    float* b1s = (float*)(smc + G_B1S);
    float* b2s = (float*)(smc + G_B2S);

    {
        const uint4* s1h = (const uint4*)g_B1hi;
        const uint4* s1l = (const uint4*)g_B1lo;
        const uint4* sxh = (const uint4*)g_Xhi + row0 * 16;
        const uint4* sxl = (const uint4*)g_Xlo + row0 * 16;
        #pragma unroll
        for (int p = 0; p < 4; ++p) {
            int q = tid + p * 512;
            int r = q >> 4, c16 = q & 15;
            u32 d = (u32)(((r << 4) + (c16 ^ (r & 7))) << 4);
            *(uint4*)(smc + G_W1HI + d) = s1h[q];
            *(uint4*)(smc + G_W1LO + d) = s1l[q];
            *(uint4*)(smc + G_XHHI + d) = sxh[q];
            *(uint4*)(smc + G_XHLO + d) = sxl[q];
        }
    }
    if (tid < 128) { b1s[tid] = gb1[tid]; b2s[tid] = gb2[tid]; }
    __syncthreads();

    const int a_ro = (lane & 7) + (lane & 8);
    const int a_co = lane >> 4;
    const int b_ro = (lane & 7) + ((lane >> 1) & 8);
    const int b_co = (lane >> 3) & 1;
    const int tq = lane >> 2;
    const int tr = (lane & 3) * 2;
    const int wm = (wid & 3) * 32;
    const int wn = (wid >> 2) * 32;

    // Layer 1 (3-term split)
    float acc[2][4][4];
    #pragma unroll
    for (int i = 0; i < 2; ++i)
        #pragma unroll
        for (int j = 0; j < 4; ++j)
            #pragma unroll
            for (int q = 0; q < 4; ++q) acc[i][j][q] = 0.0f;

    #pragma unroll
    for (int k = 0; k < 8; ++k) {
        const int kc = k * 2;
        u32 ah[2][4], al[2][4], bh[2][4], bl[2][4];
        #pragma unroll
        for (int mt = 0; mt < 2; ++mt) {
            int r = wm + mt * 16 + a_ro;
            ldsm4(ah[mt], sw_addr(sbase + G_XHHI, r, kc + a_co));
            ldsm4(al[mt], sw_addr(sbase + G_XHLO, r, kc + a_co));
        }
        #pragma unroll
        for (int ng = 0; ng < 2; ++ng) {
            int r = wn + ng * 16 + b_ro;
            ldsm4(bh[ng], sw_addr(sbase + G_W1HI, r, kc + b_co));
            ldsm4(bl[ng], sw_addr(sbase + G_W1LO, r, kc + b_co));
        }
        #pragma unroll
        for (int mt = 0; mt < 2; ++mt)
            #pragma unroll
            for (int ng = 0; ng < 2; ++ng) {
                mma16816(acc[mt][2 * ng],     ah[mt], &bh[ng][0]);
                mma16816(acc[mt][2 * ng + 1], ah[mt], &bh[ng][2]);
                mma16816(acc[mt][2 * ng],     ah[mt], &bl[ng][0]);
                mma16816(acc[mt][2 * ng + 1], ah[mt], &bl[ng][2]);
                mma16816(acc[mt][2 * ng],     al[mt], &bh[ng][0]);
                mma16816(acc[mt][2 * ng + 1], al[mt], &bh[ng][2]);
            }
    }
    __syncthreads();

    // epilogue 1: bias + gelu + hi/lo split -> XH regions
    #pragma unroll
    for (int mt = 0; mt < 2; ++mt)
        #pragma unroll
        for (int nt = 0; nt < 4; ++nt) {
            int r = wm + mt * 16 + tq;
            int c = wn + nt * 8 + tr;
            float v0 = gelu_exact(acc[mt][nt][0] + b1s[c]);
            float v1 = gelu_exact(acc[mt][nt][1] + b1s[c + 1]);
            float v2 = gelu_exact(acc[mt][nt][2] + b1s[c]);
            float v3 = gelu_exact(acc[mt][nt][3] + b1s[c + 1]);
            int c16 = c >> 3, cb = (c & 7) * 2;
            u32 d0 = sw_addr(sbase + G_XHHI, r, c16) - sbase + cb;
            u32 d8 = sw_addr(sbase + G_XHHI, r + 8, c16) - sbase + cb;
            unsigned short h0, l0, h1, l1, h2, l2, h3, l3;
            bf_split(v0, h0, l0); bf_split(v1, h1, l1);
            bf_split(v2, h2, l2); bf_split(v3, h3, l3);
            *(u32*)(smc + d0) = (u32)h0 | ((u32)h1 << 16);
            *(u32*)(smc + d8) = (u32)h2 | ((u32)h3 << 16);
            *(u32*)(smc + d0 + (G_XHLO - G_XHHI)) = (u32)l0 | ((u32)l1 << 16);
            *(u32*)(smc + d8 + (G_XHLO - G_XHHI)) = (u32)l2 | ((u32)l3 << 16);
        }

    // restage gW2^T over W1
    {
        const uint4* s2h = (const uint4*)g_B2ghi;
        const uint4* s2l = (const uint4*)g_B2glo;
        #pragma unroll
        for (int p = 0; p < 4; ++p) {
            int q = tid + p * 512;
            int r = q >> 4, c16 = q & 15;
            u32 d = (u32)(((r << 4) + (c16 ^ (r & 7))) << 4);
            *(uint4*)(smc + G_W1HI + d) = s2h[q];
            *(uint4*)(smc + G_W1LO + d) = s2l[q];
        }
    }
    __syncthreads();

    // Layer 2 (3-term split)
    float ac2[2][4][4];
    #pragma unroll
    for (int i = 0; i < 2; ++i)
        #pragma unroll
        for (int j = 0; j < 4; ++j)
            #pragma unroll
            for (int q = 0; q < 4; ++q) ac2[i][j][q] = 0.0f;
    #pragma unroll
    for (int k = 0; k < 8; ++k) {
        const int kc = k * 2;
        u32 ah[2][4], al[2][4], bh[2][4], bl[2][4];
        #pragma unroll
        for (int mt = 0; mt < 2; ++mt) {
            int r = wm + mt * 16 + a_ro;
            ldsm4(ah[mt], sw_addr(sbase + G_XHHI, r, kc + a_co));
            ldsm4(al[mt], sw_addr(sbase + G_XHLO, r, kc + a_co));
        }
        #pragma unroll
        for (int ng = 0; ng < 2; ++ng) {
            int r = wn + ng * 16 + b_ro;
            ldsm4(bh[ng], sw_addr(sbase + G_W1HI, r, kc + b_co));
            ldsm4(bl[ng], sw_addr(sbase + G_W1LO, r, kc + b_co));
        }
        #pragma unroll
        for (int mt = 0; mt < 2; ++mt)
            #pragma unroll
            for (int ng = 0; ng < 2; ++ng) {
                mma16816(ac2[mt][2 * ng],     ah[mt], &bh[ng][0]);
                mma16816(ac2[mt][2 * ng + 1], ah[mt], &bh[ng][2]);
                mma16816(ac2[mt][2 * ng],     ah[mt], &bl[ng][0]);
                mma16816(ac2[mt][2 * ng + 1], ah[mt], &bl[ng][2]);
                mma16816(ac2[mt][2 * ng],     al[mt], &bh[ng][0]);
                mma16816(ac2[mt][2 * ng + 1], al[mt], &bh[ng][2]);
            }
    }
    #pragma unroll
    for (int mt = 0; mt < 2; ++mt)
        #pragma unroll
        for (int nt = 0; nt < 4; ++nt) {
            int r = wm + mt * 16 + tq;
            int c = wn + nt * 8 + tr;
            float2 o0 = make_float2(ac2[mt][nt][0] + b2s[c],
                                    ac2[mt][nt][1] + b2s[c + 1]);
            float2 o1 = make_float2(ac2[mt][nt][2] + b2s[c],
                                    ac2[mt][nt][3] + b2s[c + 1]);
            *(float2*)(g_Vres + (size_t)(row0 + r) * 128 + c) = o0;
            *(float2*)(g_Vres + (size_t)(row0 + r + 8) * 128 + c) = o1;
            *(u32*)((__nv_bfloat16*)g_VresBf + (size_t)(row0 + r) * 128 + c) =
                pack_bf16x2(o0.x, o0.y);
            *(u32*)((__nv_bfloat16*)g_VresBf + (size_t)(row0 + r + 8) * 128 + c) =
                pack_bf16x2(o1.x, o1.y);
        }
}

// ---------------------------------------------------------------------------
// k_mlp_f: f-nets (single-term bf16). Compact smem (~70 KB) -> 2 CTAs/SM.
// grid = (128 row-tiles, 12 nets), 512 threads.
// ---------------------------------------------------------------------------
#define F_W1HI  0
#define F_XHHI  32768
#define F_F2HI  65536
#define F_B1S   69632
#define F_B2S   70144
#define SMEM_F  70656

__global__ void __launch_bounds__(512, 2) k_mlp_f(
    const float* __restrict__ fb1, const float* __restrict__ fb2) {
    const int tid = threadIdx.x;
    const int lane = tid & 31;
    const int wid = tid >> 5;
    const int m = blockIdx.y;               // 0..11 (f-net index)
    const int row0 = blockIdx.x * 128;
    const u32 sbase = smem_u32(smc);
    float* b1s = (float*)(smc + F_B1S);
    float* b2s = (float*)(smc + F_B2S);

    {
        const uint4* s1h = (const uint4*)g_B1hi + (m + 1) * 2048;
        const uint4* sxh = (const uint4*)g_Xhi + row0 * 16;
        #pragma unroll
        for (int p = 0; p < 4; ++p) {
            int q = tid + p * 512;
            int r = q >> 4, c16 = q & 15;
            u32 d = (u32)(((r << 4) + (c16 ^ (r & 7))) << 4);
            *(uint4*)(smc + F_W1HI + d) = s1h[q];
            *(uint4*)(smc + F_XHHI + d) = sxh[q];
        }
    }
    {
        const uint4* sfh = (const uint4*)g_B2fhi + m * 256;
        if (tid < 256) {
            int r = tid >> 4, c16 = tid & 15;
            u32 d = (u32)(((r << 4) + (c16 ^ (r & 7))) << 4);
            *(uint4*)(smc + F_F2HI + d) = sfh[tid];
        }
        if (tid < 128) b1s[tid] = fb1[m * 128 + tid];
        if (tid < 16)  b2s[tid] = (tid < 13) ? fb2[m * 13 + tid] : 0.0f;
    }
    __syncthreads();

    const int a_ro = (lane & 7) + (lane & 8);
    const int a_co = lane >> 4;
    const int b_ro = (lane & 7) + ((lane >> 1) & 8);
    const int b_co = (lane >> 3) & 1;
    const int tq = lane >> 2;
    const int tr = (lane & 3) * 2;
    const int wm = (wid & 3) * 32;
    const int wn = (wid >> 2) * 32;

    // Layer 1 (single term)
    float acc[2][4][4];
    #pragma unroll
    for (int i = 0; i < 2; ++i)
        #pragma unroll
        for (int j = 0; j < 4; ++j)
            #pragma unroll
            for (int q = 0; q < 4; ++q) acc[i][j][q] = 0.0f;
    #pragma unroll
    for (int k = 0; k < 8; ++k) {
        const int kc = k * 2;
        u32 ah[2][4], bh[2][4];
        #pragma unroll
        for (int mt = 0; mt < 2; ++mt)
            ldsm4(ah[mt], sw_addr(sbase + F_XHHI, wm + mt * 16 + a_ro, kc + a_co));
        #pragma unroll
        for (int ng = 0; ng < 2; ++ng)
            ldsm4(bh[ng], sw_addr(sbase + F_W1HI, wn + ng * 16 + b_ro, kc + b_co));
        #pragma unroll
        for (int mt = 0; mt < 2; ++mt)
            #pragma unroll
            for (int ng = 0; ng < 2; ++ng) {
                mma16816(acc[mt][2 * ng],     ah[mt], &bh[ng][0]);
                mma16816(acc[mt][2 * ng + 1], ah[mt], &bh[ng][2]);
            }
    }
    __syncthreads();

    // epilogue 1: bias + gelu -> H (bf16) over X region
    #pragma unroll
    for (int mt = 0; mt < 2; ++mt)
        #pragma unroll
        for (int nt = 0; nt < 4; ++nt) {
            int r = wm + mt * 16 + tq;
            int c = wn + nt * 8 + tr;
            float v0 = gelu_exact(acc[mt][nt][0] + b1s[c]);
            float v1 = gelu_exact(acc[mt][nt][1] + b1s[c + 1]);
            float v2 = gelu_exact(acc[mt][nt][2] + b1s[c]);
            float v3 = gelu_exact(acc[mt][nt][3] + b1s[c + 1]);
            int c16 = c >> 3, cb = (c & 7) * 2;
            u32 d0 = sw_addr(sbase + F_XHHI, r, c16) - sbase + cb;
            u32 d8 = sw_addr(sbase + F_XHHI, r + 8, c16) - sbase + cb;
            *(u32*)(smc + d0) = pack_bf16x2(v0, v1);
            *(u32*)(smc + d8) = pack_bf16x2(v2, v3);
        }
    __syncthreads();

    // Layer 2: W_all = H @ fW2 (N=16 padded), warps 0-7
    if (wid < 8) {
        const int wm2 = wid * 16;
        float ac2[2][4];
        #pragma unroll
        for (int j = 0; j < 2; ++j)
            #pragma unroll
            for (int q = 0; q < 4; ++q) ac2[j][q] = 0.0f;
        #pragma unroll
        for (int k = 0; k < 8; ++k) {
            const int kc = k * 2;
            u32 ah[4], bh[4];
            ldsm4(ah, sw_addr(sbase + F_XHHI, wm2 + a_ro, kc + a_co));
            ldsm4(bh, sw_addr(sbase + F_F2HI, b_ro, kc + b_co));
            mma16816(ac2[0], ah, &bh[0]);
            mma16816(ac2[1], ah, &bh[2]);
        }
        float* op = g_Wall + (size_t)m * R_TOT * K_LNK + (size_t)row0 * K_LNK;
        #pragma unroll
        for (int nt = 0; nt < 2; ++nt) {
            int c = nt * 8 + tr;
            int r = wm2 + tq;
            if (c < 13) {
                op[(r) * K_LNK + c]     = ac2[nt][0] + b2s[c];
                op[(r + 8) * K_LNK + c] = ac2[nt][2] + b2s[c];
            }
            if (c + 1 < 13) {
                op[(r) * K_LNK + c + 1]     = ac2[nt][1] + b2s[c + 1];
                op[(r + 8) * K_LNK + c + 1] = ac2[nt][3] + b2s[c + 1];
            }
        }
    }
}

// ---------------------------------------------------------------------------
// k_scan: chord-mix step, TWO rows per warp (R11 proven form).
// ---------------------------------------------------------------------------
__global__ void __launch_bounds__(256) k_scan(int m, const int* __restrict__ cols,
                                              float* __restrict__ out_final) {
    const __nv_bfloat16* Vin = (m == 0) ? g_VresBf
                                        : ((m & 1) ? g_Vbf1 : g_Vbf0);
    __nv_bfloat16* Vout = ((m + 1) & 1) ? g_Vbf1 : g_Vbf0;
    const float* Wm = g_Wall + (size_t)m * R_TOT * K_LNK;

    const int lane = threadIdx.x & 31;
    const int pair = (blockIdx.x * blockDim.x + threadIdx.x) >> 5;
    const int hl   = lane & 15;
    const int lr   = pair * 2 + (lane >> 4);

    u32 wv = 0; int iv = 0;
    if (hl < K_LNK) {
        float w = Wm[lr * K_LNK + hl];
        wv = pack_bf16x2(w, w);
        int s = lr & (S_LEN - 1), b = lr >> 12;
        iv = ((b << 12) | cols[s * K_LNK + hl]) << 4;
    }

    const uint4* Vin4 = (const uint4*)Vin;
    u32 a0 = 0, a1 = 0, a2 = 0, a3 = 0;
    const int selk = lane & 16;
    #pragma unroll
    for (int k = 0; k < K_LNK; ++k) {
        u32 wk = __shfl_sync(0xffffffffu, wv, k | selk);
        int ik = __shfl_sync(0xffffffffu, iv, k | selk);
        uint4 v = Vin4[ik + hl];
        fma_bf2(a0, v.x, wk);
        fma_bf2(a1, v.y, wk);
        fma_bf2(a2, v.z, wk);
        fma_bf2(a3, v.w, wk);
    }

    if (m == M_NET - 1) {
        const float4* res4 = (const float4*)g_Vres + ((size_t)lr << 5);
        float4 r0 = res4[hl * 2], r1 = res4[hl * 2 + 1];
        r0.x += __uint_as_float(a0 << 16);
        r0.y += __uint_as_float(a0 & 0xFFFF0000u);
        r0.z += __uint_as_float(a1 << 16);
        r0.w += __uint_as_float(a1 & 0xFFFF0000u);
        r1.x += __uint_as_float(a2 << 16);
        r1.y += __uint_as_float(a2 & 0xFFFF0000u);
        r1.z += __uint_as_float(a3 << 16);
        r1.w += __uint_as_float(a3 & 0xFFFF0000u);
        float4* op = (float4*)out_final + ((size_t)lr << 5);
        op[hl * 2]     = r0;
        op[hl * 2 + 1] = r1;
    } else {
        uint4 r = ((const uint4*)g_VresBf)[((size_t)lr << 4) + hl];
        uint4 o;
        o.x = add_bf2(r.x, a0);
        o.y = add_bf2(r.y, a1);
        o.z = add_bf2(r.z, a2);
        o.w = add_bf2(r.w, a3);
        ((uint4*)Vout)[((size_t)lr << 4) + hl] = o;
    }
}

// ---------------------------------------------------------------------------
extern "C" void kernel_launch(void* const* d_in, const int* in_sizes, int n_in,
                              void* d_out, int out_size) {
    const int*   data = (const int*)  d_in[0];
    const int*   cols = (const int*)  d_in[1];
    const float* emb  = (const float*)d_in[2];
    const float* apc  = (const float*)d_in[3];
    const float* gW1  = (const float*)d_in[4];
    const float* gb1  = (const float*)d_in[5];
    const float* gW2  = (const float*)d_in[6];
    const float* gb2  = (const float*)d_in[7];
    const float* fW1  = (const float*)d_in[8];
    const float* fb1  = (const float*)d_in[9];
    const float* fW2  = (const float*)d_in[10];
    const float* fb2  = (const float*)d_in[11];
    float* out = (float*)d_out;

    cudaFuncSetAttribute(k_mlp_g, cudaFuncAttributeMaxDynamicSharedMemorySize,
                         SMEM_G);
    cudaFuncSetAttribute(k_mlp_f, cudaFuncAttributeMaxDynamicSharedMemorySize,
                         SMEM_F);

    // 1) fused weight prep + embeddings
    k_init<<<(INIT_TOT + 255) / 256, 256>>>(gW1, gW2, fW1, fW2,
                                            data, emb, apc);

    // 2) f-nets (2 CTAs/SM) then g-net (1 CTA/SM, 140 KB)
    dim3 grid_f(R_TOT / 128, 12);
    k_mlp_f<<<grid_f, 512, SMEM_F>>>(fb1, fb2);
    k_mlp_g<<<R_TOT / 128, 512, SMEM_G>>>(gb1, gb2);

    // 3) 12 chord-mix scan steps (R11 proven form)
    for (int m = 0; m < M_NET; ++m)
        k_scan<<<R_TOT / 16, 256>>>(m, cols, out);
}

// round 15
// speedup vs baseline: 1.2129x; 1.0578x over previous
#include <cuda_runtime.h>
#include <cuda_bf16.h>
#include <cuda_fp16.h>
#include <math.h>
#include <stdint.h>

#define R_TOT 16384
#define S_LEN 4096
#define D_DIM 128
#define K_LNK 13
#define M_NET 12
#define F8_SCALE 256.0f
#define F8_INV   0.00390625f

typedef unsigned int u32;
typedef unsigned short u16;
typedef unsigned char u8;
typedef unsigned long long u64;

// ---------------- scratch (static device memory only) ----------------------
__device__ __nv_bfloat16 g_Xhi[R_TOT * D_DIM];          // X hi, row-major
__device__ __nv_bfloat16 g_Xlo[R_TOT * D_DIM];          // X lo
__device__ __nv_bfloat16 g_B1hi[13 * 128 * 128];        // W1^T [net][n][k]
__device__ __nv_bfloat16 g_B1lo[13 * 128 * 128];
__device__ __nv_bfloat16 g_B2ghi[128 * 128];            // gW2^T [n][k]
__device__ __nv_bfloat16 g_B2glo[128 * 128];
__device__ __nv_bfloat16 g_B2fhi[12 * 16 * 128];        // fW2^T padded N=16
__device__ float g_Vres[R_TOT * D_DIM];                 // fp32 residual (exact)
__device__ u16   g_VH[R_TOT * D_DIM];                   // half residual * 256
__device__ u8    g_Vf8a[R_TOT * D_DIM];                 // fp8 V ping (* 256)
__device__ u8    g_Vf8b[R_TOT * D_DIM];                 // fp8 V pong (* 256)
__device__ float g_Wall[M_NET * R_TOT * K_LNK];

// ---------------- helpers ---------------------------------------------------
__device__ __forceinline__ u32 smem_u32(const void* p) {
    u32 a;
    asm("{ .reg .u64 t; cvta.to.shared.u64 t, %1; cvt.u32.u64 %0, t; }"
        : "=r"(a) : "l"(p));
    return a;
}
__device__ __forceinline__ void ldsm4(u32* r, u32 addr) {
    asm volatile("ldmatrix.sync.aligned.m8n8.x4.shared.b16 {%0,%1,%2,%3}, [%4];"
        : "=r"(r[0]), "=r"(r[1]), "=r"(r[2]), "=r"(r[3]) : "r"(addr));
}
__device__ __forceinline__ void mma16816(float* d, const u32* a, const u32* b) {
    asm volatile(
        "mma.sync.aligned.m16n8k16.row.col.f32.bf16.bf16.f32 "
        "{%0,%1,%2,%3}, {%4,%5,%6,%7}, {%8,%9}, {%0,%1,%2,%3};"
        : "+f"(d[0]), "+f"(d[1]), "+f"(d[2]), "+f"(d[3])
        : "r"(a[0]), "r"(a[1]), "r"(a[2]), "r"(a[3]), "r"(b[0]), "r"(b[1]));
}
// swizzled byte address of 16B unit (r, c16) in a [rows][128]bf16 smem tile
__device__ __forceinline__ u32 sw_addr(u32 base, int r, int c16) {
    return base + (u32)(((r << 4) + (c16 ^ (r & 7))) << 4);
}
__device__ __forceinline__ void bf_split(float v, u16& h, u16& l) {
    __nv_bfloat16 hb = __float2bfloat16(v);
    __nv_bfloat16 lb = __float2bfloat16(v - __bfloat162float(hb));
    h = __bfloat16_as_ushort(hb);
    l = __bfloat16_as_ushort(lb);
}
// pack two fp32 -> bf16x2 (lo arg in low half = memory-first element)
__device__ __forceinline__ u32 pack_bf16x2(float lo, float hi) {
    u32 r;
    asm("cvt.rn.bf16x2.f32 %0, %1, %2;" : "=r"(r) : "f"(hi), "f"(lo));
    return r;
}
// pack two fp32 -> f16x2 (lo arg in low half)
__device__ __forceinline__ u32 f32_to_h2(float lo, float hi) {
    u32 r;
    asm("cvt.rn.f16x2.f32 %0, %1, %2;" : "=r"(r) : "f"(hi), "f"(lo));
    return r;
}
// 4 packed e4m3 (u32) -> two f16x2
__device__ __forceinline__ void f8_to_h2(u32 p, u32& a, u32& b) {
    u16 lo, hi;
    asm("mov.b32 {%0,%1}, %2;" : "=h"(lo), "=h"(hi) : "r"(p));
    asm("cvt.rn.f16x2.e4m3x2 %0, %1;" : "=r"(a) : "h"(lo));
    asm("cvt.rn.f16x2.e4m3x2 %0, %1;" : "=r"(b) : "h"(hi));
}
// f16x2 -> 2 packed e4m3
__device__ __forceinline__ u16 h2_to_f8(u32 h2) {
    u16 r;
    asm("cvt.rn.satfinite.e4m3x2.f16x2 %0, %1;" : "=h"(r) : "r"(h2));
    return r;
}
__device__ __forceinline__ u32 pack_u16x2(u16 a, u16 b) {
    u32 r;
    asm("mov.b32 %0, {%1,%2};" : "=r"(r) : "h"(a), "h"(b));
    return r;
}
__device__ __forceinline__ void hfma2(u32& d, u32 a, u32 b) {
    asm("fma.rn.f16x2 %0, %1, %2, %0;" : "+r"(d) : "r"(a), "r"(b));
}
__device__ __forceinline__ u32 hadd2(u32 a, u32 b) {
    u32 r;
    asm("add.rn.f16x2 %0, %1, %2;" : "=r"(r) : "r"(a), "r"(b));
    return r;
}
__device__ __forceinline__ float gelu_exact(float x) {
    return 0.5f * x * (1.0f + erff(x * 0.70710678118654752440f));
}

// ---------------------------------------------------------------------------
// Fused init: weight prep (transpose + bf16 split) + embeddings.
// ---------------------------------------------------------------------------
#define PREP_A (13 * 128 * 64)
#define PREP_B (128 * 64)
#define PREP_C (12 * 16 * 64)
#define PREP_TOT (PREP_A + PREP_B + PREP_C)
#define EMB_TOT (R_TOT * 16)
#define INIT_TOT (PREP_TOT + EMB_TOT)

__global__ void k_init(const float* __restrict__ gW1,
                       const float* __restrict__ gW2,
                       const float* __restrict__ fW1,
                       const float* __restrict__ fW2,
                       const int* __restrict__ data,
                       const float* __restrict__ emb,
                       const float* __restrict__ apc) {
    int t = blockIdx.x * blockDim.x + threadIdx.x;
    if (t < PREP_TOT) {
        float w0, w1;
        if (t < PREP_A) {
            int net = t >> 13;
            int r = t & 8191;
            int n = r >> 6, k = (r & 63) * 2;
            const float* W1 = (net == 0) ? gW1
                                         : fW1 + (size_t)(net - 1) * 128 * 128;
            w0 = W1[k * 128 + n];
            w1 = W1[(k + 1) * 128 + n];
            int widx = (net * 128 + n) * 64 + (k >> 1);
            u16 h0, l0, h1, l1;
            bf_split(w0, h0, l0); bf_split(w1, h1, l1);
            ((u32*)g_B1hi)[widx] = (u32)h0 | ((u32)h1 << 16);
            ((u32*)g_B1lo)[widx] = (u32)l0 | ((u32)l1 << 16);
        } else if (t < PREP_A + PREP_B) {
            int r = t - PREP_A;
            int n = r >> 6, k = (r & 63) * 2;
            w0 = gW2[k * 128 + n];
            w1 = gW2[(k + 1) * 128 + n];
            int widx = n * 64 + (k >> 1);
            u16 h0, l0, h1, l1;
            bf_split(w0, h0, l0); bf_split(w1, h1, l1);
            ((u32*)g_B2ghi)[widx] = (u32)h0 | ((u32)h1 << 16);
            ((u32*)g_B2glo)[widx] = (u32)l0 | ((u32)l1 << 16);
        } else {
            int r = t - PREP_A - PREP_B;
            int net = r >> 10;
            int rr = r & 1023;
            int n = rr >> 6, k = (rr & 63) * 2;
            w0 = (n < 13) ? fW2[(size_t)net * 128 * 13 + k * 13 + n] : 0.0f;
            w1 = (n < 13) ? fW2[(size_t)net * 128 * 13 + (k + 1) * 13 + n] : 0.0f;
            ((u32*)g_B2fhi)[(net * 16 + n) * 64 + (k >> 1)] =
                pack_bf16x2(w0, w1);
        }
    } else {
        int idx = t - PREP_TOT;
        if (idx >= EMB_TOT) return;
        int row = idx >> 4;
        int g8 = idx & 15;
        int tok = data[row];
        int s = row & (S_LEN - 1);
        float4 e0 = ((const float4*)emb)[tok * 32 + g8 * 2];
        float4 e1 = ((const float4*)emb)[tok * 32 + g8 * 2 + 1];
        float4 a0 = ((const float4*)apc)[s * 32 + g8 * 2];
        float4 a1 = ((const float4*)apc)[s * 32 + g8 * 2 + 1];
        float v[8] = {e0.x + a0.x, e0.y + a0.y, e0.z + a0.z, e0.w + a0.w,
                      e1.x + a1.x, e1.y + a1.y, e1.z + a1.z, e1.w + a1.w};
        u32 hp[4], lp[4];
        #pragma unroll
        for (int p = 0; p < 4; ++p) {
            u16 h0, l0, h1, l1;
            bf_split(v[2 * p], h0, l0);
            bf_split(v[2 * p + 1], h1, l1);
            hp[p] = (u32)h0 | ((u32)h1 << 16);
            lp[p] = (u32)l0 | ((u32)l1 << 16);
        }
        ((uint4*)g_Xhi)[row * 16 + g8] = make_uint4(hp[0], hp[1], hp[2], hp[3]);
        ((uint4*)g_Xlo)[row * 16 + g8] = make_uint4(lp[0], lp[1], lp[2], lp[3]);
    }
}

// ---------------------------------------------------------------------------
// k_mlp_g: g-net only (3-term bf16 hi/lo split, fp32 backbone).
// grid = 128 row-tiles, 512 threads, 132 KB smem (1 CTA/SM).
// ---------------------------------------------------------------------------
#define G_W1HI  0
#define G_W1LO  32768
#define G_XHHI  65536
#define G_XHLO  98304
#define G_B1S   131072
#define G_B2S   131584
#define SMEM_G  132096

extern __shared__ char smc[];

__global__ void __launch_bounds__(512, 1) k_mlp_g(
    const float* __restrict__ gb1, const float* __restrict__ gb2) {
    const int tid = threadIdx.x;
    const int lane = tid & 31;
    const int wid = tid >> 5;
    const int row0 = blockIdx.x * 128;
    const u32 sbase = smem_u32(smc);
    float* b1s = (float*)(smc + G_B1S);
    float* b2s = (float*)(smc + G_B2S);

    {
        const uint4* s1h = (const uint4*)g_B1hi;
        const uint4* s1l = (const uint4*)g_B1lo;
        const uint4* sxh = (const uint4*)g_Xhi + row0 * 16;
        const uint4* sxl = (const uint4*)g_Xlo + row0 * 16;
        #pragma unroll
        for (int p = 0; p < 4; ++p) {
            int q = tid + p * 512;
            int r = q >> 4, c16 = q & 15;
            u32 d = (u32)(((r << 4) + (c16 ^ (r & 7))) << 4);
            *(uint4*)(smc + G_W1HI + d) = s1h[q];
            *(uint4*)(smc + G_W1LO + d) = s1l[q];
            *(uint4*)(smc + G_XHHI + d) = sxh[q];
            *(uint4*)(smc + G_XHLO + d) = sxl[q];
        }
    }
    if (tid < 128) { b1s[tid] = gb1[tid]; b2s[tid] = gb2[tid]; }
    __syncthreads();

    const int a_ro = (lane & 7) + (lane & 8);
    const int a_co = lane >> 4;
    const int b_ro = (lane & 7) + ((lane >> 1) & 8);
    const int b_co = (lane >> 3) & 1;
    const int tq = lane >> 2;
    const int tr = (lane & 3) * 2;
    const int wm = (wid & 3) * 32;
    const int wn = (wid >> 2) * 32;

    // Layer 1 (3-term split)
    float acc[2][4][4];
    #pragma unroll
    for (int i = 0; i < 2; ++i)
        #pragma unroll
        for (int j = 0; j < 4; ++j)
            #pragma unroll
            for (int q = 0; q < 4; ++q) acc[i][j][q] = 0.0f;

    #pragma unroll
    for (int k = 0; k < 8; ++k) {
        const int kc = k * 2;
        u32 ah[2][4], al[2][4], bh[2][4], bl[2][4];
        #pragma unroll
        for (int mt = 0; mt < 2; ++mt) {
            int r = wm + mt * 16 + a_ro;
            ldsm4(ah[mt], sw_addr(sbase + G_XHHI, r, kc + a_co));
            ldsm4(al[mt], sw_addr(sbase + G_XHLO, r, kc + a_co));
        }
        #pragma unroll
        for (int ng = 0; ng < 2; ++ng) {
            int r = wn + ng * 16 + b_ro;
            ldsm4(bh[ng], sw_addr(sbase + G_W1HI, r, kc + b_co));
            ldsm4(bl[ng], sw_addr(sbase + G_W1LO, r, kc + b_co));
        }
        #pragma unroll
        for (int mt = 0; mt < 2; ++mt)
            #pragma unroll
            for (int ng = 0; ng < 2; ++ng) {
                mma16816(acc[mt][2 * ng],     ah[mt], &bh[ng][0]);
                mma16816(acc[mt][2 * ng + 1], ah[mt], &bh[ng][2]);
                mma16816(acc[mt][2 * ng],     ah[mt], &bl[ng][0]);
                mma16816(acc[mt][2 * ng + 1], ah[mt], &bl[ng][2]);
                mma16816(acc[mt][2 * ng],     al[mt], &bh[ng][0]);
                mma16816(acc[mt][2 * ng + 1], al[mt], &bh[ng][2]);
            }
    }
    __syncthreads();

    // epilogue 1: bias + gelu + hi/lo split -> XH regions
    #pragma unroll
    for (int mt = 0; mt < 2; ++mt)
        #pragma unroll
        for (int nt = 0; nt < 4; ++nt) {
            int r = wm + mt * 16 + tq;
            int c = wn + nt * 8 + tr;
            float v0 = gelu_exact(acc[mt][nt][0] + b1s[c]);
            float v1 = gelu_exact(acc[mt][nt][1] + b1s[c + 1]);
            float v2 = gelu_exact(acc[mt][nt][2] + b1s[c]);
            float v3 = gelu_exact(acc[mt][nt][3] + b1s[c + 1]);
            int c16 = c >> 3, cb = (c & 7) * 2;
            u32 d0 = sw_addr(sbase + G_XHHI, r, c16) - sbase + cb;
            u32 d8 = sw_addr(sbase + G_XHHI, r + 8, c16) - sbase + cb;
            u16 h0, l0, h1, l1, h2, l2, h3, l3;
            bf_split(v0, h0, l0); bf_split(v1, h1, l1);
            bf_split(v2, h2, l2); bf_split(v3, h3, l3);
            *(u32*)(smc + d0) = (u32)h0 | ((u32)h1 << 16);
            *(u32*)(smc + d8) = (u32)h2 | ((u32)h3 << 16);
            *(u32*)(smc + d0 + (G_XHLO - G_XHHI)) = (u32)l0 | ((u32)l1 << 16);
            *(u32*)(smc + d8 + (G_XHLO - G_XHHI)) = (u32)l2 | ((u32)l3 << 16);
        }

    // restage gW2^T over W1
    {
        const uint4* s2h = (const uint4*)g_B2ghi;
        const uint4* s2l = (const uint4*)g_B2glo;
        #pragma unroll
        for (int p = 0; p < 4; ++p) {
            int q = tid + p * 512;
            int r = q >> 4, c16 = q & 15;
            u32 d = (u32)(((r << 4) + (c16 ^ (r & 7))) << 4);
            *(uint4*)(smc + G_W1HI + d) = s2h[q];
            *(uint4*)(smc + G_W1LO + d) = s2l[q];
        }
    }
    __syncthreads();

    // Layer 2 (3-term split)
    float ac2[2][4][4];
    #pragma unroll
    for (int i = 0; i < 2; ++i)
        #pragma unroll
        for (int j = 0; j < 4; ++j)
            #pragma unroll
            for (int q = 0; q < 4; ++q) ac2[i][j][q] = 0.0f;
    #pragma unroll
    for (int k = 0; k < 8; ++k) {
        const int kc = k * 2;
        u32 ah[2][4], al[2][4], bh[2][4], bl[2][4];
        #pragma unroll
        for (int mt = 0; mt < 2; ++mt) {
            int r = wm + mt * 16 + a_ro;
            ldsm4(ah[mt], sw_addr(sbase + G_XHHI, r, kc + a_co));
            ldsm4(al[mt], sw_addr(sbase + G_XHLO, r, kc + a_co));
        }
        #pragma unroll
        for (int ng = 0; ng < 2; ++ng) {
            int r = wn + ng * 16 + b_ro;
            ldsm4(bh[ng], sw_addr(sbase + G_W1HI, r, kc + b_co));
            ldsm4(bl[ng], sw_addr(sbase + G_W1LO, r, kc + b_co));
        }
        #pragma unroll
        for (int mt = 0; mt < 2; ++mt)
            #pragma unroll
            for (int ng = 0; ng < 2; ++ng) {
                mma16816(ac2[mt][2 * ng],     ah[mt], &bh[ng][0]);
                mma16816(ac2[mt][2 * ng + 1], ah[mt], &bh[ng][2]);
                mma16816(ac2[mt][2 * ng],     ah[mt], &bl[ng][0]);
                mma16816(ac2[mt][2 * ng + 1], ah[mt], &bl[ng][2]);
                mma16816(ac2[mt][2 * ng],     al[mt], &bh[ng][0]);
                mma16816(ac2[mt][2 * ng + 1], al[mt], &bh[ng][2]);
            }
    }
    #pragma unroll
    for (int mt = 0; mt < 2; ++mt)
        #pragma unroll
        for (int nt = 0; nt < 4; ++nt) {
            int r = wm + mt * 16 + tq;
            int c = wn + nt * 8 + tr;
            float2 o0 = make_float2(ac2[mt][nt][0] + b2s[c],
                                    ac2[mt][nt][1] + b2s[c + 1]);
            float2 o1 = make_float2(ac2[mt][nt][2] + b2s[c],
                                    ac2[mt][nt][3] + b2s[c + 1]);
            size_t i0 = (size_t)(row0 + r) * 128 + c;
            size_t i1 = (size_t)(row0 + r + 8) * 128 + c;
            *(float2*)(g_Vres + i0) = o0;
            *(float2*)(g_Vres + i1) = o1;
            // scaled half residual + fp8 seed for the scan
            u32 hs0 = f32_to_h2(o0.x * F8_SCALE, o0.y * F8_SCALE);
            u32 hs1 = f32_to_h2(o1.x * F8_SCALE, o1.y * F8_SCALE);
            *(u32*)(g_VH + i0) = hs0;
            *(u32*)(g_VH + i1) = hs1;
            *(u16*)(g_Vf8a + i0) = h2_to_f8(hs0);
            *(u16*)(g_Vf8a + i1) = h2_to_f8(hs1);
        }
}

// ---------------------------------------------------------------------------
// k_mlp_f: f-nets (single-term bf16). Compact smem (~70 KB) -> 2 CTAs/SM.
// grid = (128 row-tiles, 12 nets), 512 threads.
// ---------------------------------------------------------------------------
#define F_W1HI  0
#define F_XHHI  32768
#define F_F2HI  65536
#define F_B1S   69632
#define F_B2S   70144
#define SMEM_F  70656

__global__ void __launch_bounds__(512, 2) k_mlp_f(
    const float* __restrict__ fb1, const float* __restrict__ fb2) {
    const int tid = threadIdx.x;
    const int lane = tid & 31;
    const int wid = tid >> 5;
    const int m = blockIdx.y;               // 0..11 (f-net index)
    const int row0 = blockIdx.x * 128;
    const u32 sbase = smem_u32(smc);
    float* b1s = (float*)(smc + F_B1S);
    float* b2s = (float*)(smc + F_B2S);

    {
        const uint4* s1h = (const uint4*)g_B1hi + (m + 1) * 2048;
        const uint4* sxh = (const uint4*)g_Xhi + row0 * 16;
        #pragma unroll
        for (int p = 0; p < 4; ++p) {
            int q = tid + p * 512;
            int r = q >> 4, c16 = q & 15;
            u32 d = (u32)(((r << 4) + (c16 ^ (r & 7))) << 4);
            *(uint4*)(smc + F_W1HI + d) = s1h[q];
            *(uint4*)(smc + F_XHHI + d) = sxh[q];
        }
    }
    {
        const uint4* sfh = (const uint4*)g_B2fhi + m * 256;
        if (tid < 256) {
            int r = tid >> 4, c16 = tid & 15;
            u32 d = (u32)(((r << 4) + (c16 ^ (r & 7))) << 4);
            *(uint4*)(smc + F_F2HI + d) = sfh[tid];
        }
        if (tid < 128) b1s[tid] = fb1[m * 128 + tid];
        if (tid < 16)  b2s[tid] = (tid < 13) ? fb2[m * 13 + tid] : 0.0f;
    }
    __syncthreads();

    const int a_ro = (lane & 7) + (lane & 8);
    const int a_co = lane >> 4;
    const int b_ro = (lane & 7) + ((lane >> 1) & 8);
    const int b_co = (lane >> 3) & 1;
    const int tq = lane >> 2;
    const int tr = (lane & 3) * 2;
    const int wm = (wid & 3) * 32;
    const int wn = (wid >> 2) * 32;

    // Layer 1 (single term)
    float acc[2][4][4];
    #pragma unroll
    for (int i = 0; i < 2; ++i)
        #pragma unroll
        for (int j = 0; j < 4; ++j)
            #pragma unroll
            for (int q = 0; q < 4; ++q) acc[i][j][q] = 0.0f;
    #pragma unroll
    for (int k = 0; k < 8; ++k) {
        const int kc = k * 2;
        u32 ah[2][4], bh[2][4];
        #pragma unroll
        for (int mt = 0; mt < 2; ++mt)
            ldsm4(ah[mt], sw_addr(sbase + F_XHHI, wm + mt * 16 + a_ro, kc + a_co));
        #pragma unroll
        for (int ng = 0; ng < 2; ++ng)
            ldsm4(bh[ng], sw_addr(sbase + F_W1HI, wn + ng * 16 + b_ro, kc + b_co));
        #pragma unroll
        for (int mt = 0; mt < 2; ++mt)
            #pragma unroll
            for (int ng = 0; ng < 2; ++ng) {
                mma16816(acc[mt][2 * ng],     ah[mt], &bh[ng][0]);
                mma16816(acc[mt][2 * ng + 1], ah[mt], &bh[ng][2]);
            }
    }
    __syncthreads();

    // epilogue 1: bias + gelu -> H (bf16) over X region
    #pragma unroll
    for (int mt = 0; mt < 2; ++mt)
        #pragma unroll
        for (int nt = 0; nt < 4; ++nt) {
            int r = wm + mt * 16 + tq;
            int c = wn + nt * 8 + tr;
            float v0 = gelu_exact(acc[mt][nt][0] + b1s[c]);
            float v1 = gelu_exact(acc[mt][nt][1] + b1s[c + 1]);
            float v2 = gelu_exact(acc[mt][nt][2] + b1s[c]);
            float v3 = gelu_exact(acc[mt][nt][3] + b1s[c + 1]);
            int c16 = c >> 3, cb = (c & 7) * 2;
            u32 d0 = sw_addr(sbase + F_XHHI, r, c16) - sbase + cb;
            u32 d8 = sw_addr(sbase + F_XHHI, r + 8, c16) - sbase + cb;
            *(u32*)(smc + d0) = pack_bf16x2(v0, v1);
            *(u32*)(smc + d8) = pack_bf16x2(v2, v3);
        }
    __syncthreads();

    // Layer 2: W_all = H @ fW2 (N=16 padded), warps 0-7
    if (wid < 8) {
        const int wm2 = wid * 16;
        float ac2[2][4];
        #pragma unroll
        for (int j = 0; j < 2; ++j)
            #pragma unroll
            for (int q = 0; q < 4; ++q) ac2[j][q] = 0.0f;
        #pragma unroll
        for (int k = 0; k < 8; ++k) {
            const int kc = k * 2;
            u32 ah[4], bh[4];
            ldsm4(ah, sw_addr(sbase + F_XHHI, wm2 + a_ro, kc + a_co));
            ldsm4(bh, sw_addr(sbase + F_F2HI, b_ro, kc + b_co));
            mma16816(ac2[0], ah, &bh[0]);
            mma16816(ac2[1], ah, &bh[2]);
        }
        float* op = g_Wall + (size_t)m * R_TOT * K_LNK + (size_t)row0 * K_LNK;
        #pragma unroll
        for (int nt = 0; nt < 2; ++nt) {
            int c = nt * 8 + tr;
            int r = wm2 + tq;
            if (c < 13) {
                op[(r) * K_LNK + c]     = ac2[nt][0] + b2s[c];
                op[(r + 8) * K_LNK + c] = ac2[nt][2] + b2s[c];
            }
            if (c + 1 < 13) {
                op[(r) * K_LNK + c + 1]     = ac2[nt][1] + b2s[c + 1];
                op[(r + 8) * K_LNK + c + 1] = ac2[nt][3] + b2s[c + 1];
            }
        }
    }
}

// ---------------------------------------------------------------------------
// k_scan: chord-mix step with fp8 gathers (scaled by 256), f16x2 mix accum.
// TWO rows per warp: lanes 0-15 row A (8 fp8 each via uint2), 16-31 row B.
// Intermediate: out_f8 = f8(resH + acc)  (resH = half residual * 256).
// Final: out_f32 = res_f32 + acc / 256.
// ---------------------------------------------------------------------------
__global__ void __launch_bounds__(256) k_scan(int m, const int* __restrict__ cols,
                                              float* __restrict__ out_final) {
    const u8* Vin = (m & 1) ? g_Vf8b : g_Vf8a;
    u8* Vout = (m & 1) ? g_Vf8a : g_Vf8b;
    const float* Wm = g_Wall + (size_t)m * R_TOT * K_LNK;

    const int lane = threadIdx.x & 31;
    const int pair = (blockIdx.x * blockDim.x + threadIdx.x) >> 5;
    const int hl   = lane & 15;
    const int lr   = pair * 2 + (lane >> 4);

    u32 wv = 0; int iv = 0;
    if (hl < K_LNK) {
        float w = Wm[lr * K_LNK + hl];
        wv = f32_to_h2(w, w);
        int s = lr & (S_LEN - 1), b = lr >> 12;
        iv = ((b << 12) | cols[s * K_LNK + hl]) << 4;  // uint2 row base (16/row)
    }

    const uint2* Vin2 = (const uint2*)Vin;
    u32 a0 = 0, a1 = 0, a2 = 0, a3 = 0;     // f16x2 mix accumulators (*256)
    const int selk = lane & 16;
    #pragma unroll
    for (int k = 0; k < K_LNK; ++k) {
        u32 wk = __shfl_sync(0xffffffffu, wv, k | selk);
        int ik = __shfl_sync(0xffffffffu, iv, k | selk);
        uint2 v = Vin2[ik + hl];
        u32 h0, h1, h2, h3;
        f8_to_h2(v.x, h0, h1);
        f8_to_h2(v.y, h2, h3);
        hfma2(a0, h0, wk);
        hfma2(a1, h1, wk);
        hfma2(a2, h2, wk);
        hfma2(a3, h3, wk);
    }

    if (m == M_NET - 1) {
        const float4* res4 = (const float4*)g_Vres + ((size_t)lr << 5);
        float4 r0 = res4[hl * 2], r1 = res4[hl * 2 + 1];
        float2 f0 = __half22float2(*(__half2*)&a0);
        float2 f1 = __half22float2(*(__half2*)&a1);
        float2 f2 = __half22float2(*(__half2*)&a2);
        float2 f3 = __half22float2(*(__half2*)&a3);
        r0.x += f0.x * F8_INV; r0.y += f0.y * F8_INV;
        r0.z += f1.x * F8_INV; r0.w += f1.y * F8_INV;
        r1.x += f2.x * F8_INV; r1.y += f2.y * F8_INV;
        r1.z += f3.x * F8_INV; r1.w += f3.y * F8_INV;
        float4* op = (float4*)out_final + ((size_t)lr << 5);
        op[hl * 2]     = r0;
        op[hl * 2 + 1] = r1;
    } else {
        uint4 rh = ((const uint4*)g_VH)[((size_t)lr << 4) + hl];
        u16 s0 = h2_to_f8(hadd2(rh.x, a0));
        u16 s1 = h2_to_f8(hadd2(rh.y, a1));
        u16 s2 = h2_to_f8(hadd2(rh.z, a2));
        u16 s3 = h2_to_f8(hadd2(rh.w, a3));
        uint2 ov;
        ov.x = pack_u16x2(s0, s1);
        ov.y = pack_u16x2(s2, s3);
        ((uint2*)Vout)[((size_t)lr << 4) + hl] = ov;
    }
}

// ---------------------------------------------------------------------------
extern "C" void kernel_launch(void* const* d_in, const int* in_sizes, int n_in,
                              void* d_out, int out_size) {
    const int*   data = (const int*)  d_in[0];
    const int*   cols = (const int*)  d_in[1];
    const float* emb  = (const float*)d_in[2];
    const float* apc  = (const float*)d_in[3];
    const float* gW1  = (const float*)d_in[4];
    const float* gb1  = (const float*)d_in[5];
    const float* gW2  = (const float*)d_in[6];
    const float* gb2  = (const float*)d_in[7];
    const float* fW1  = (const float*)d_in[8];
    const float* fb1  = (const float*)d_in[9];
    const float* fW2  = (const float*)d_in[10];
    const float* fb2  = (const float*)d_in[11];
    float* out = (float*)d_out;

    cudaFuncSetAttribute(k_mlp_g, cudaFuncAttributeMaxDynamicSharedMemorySize,
                         SMEM_G);
    cudaFuncSetAttribute(k_mlp_f, cudaFuncAttributeMaxDynamicSharedMemorySize,
                         SMEM_F);

    // 1) fused weight prep + embeddings
    k_init<<<(INIT_TOT + 255) / 256, 256>>>(gW1, gW2, fW1, fW2,
                                            data, emb, apc);

    // 2) f-nets (2 CTAs/SM) then g-net (1 CTA/SM)
    dim3 grid_f(R_TOT / 128, 12);
    k_mlp_f<<<grid_f, 512, SMEM_F>>>(fb1, fb2);
    k_mlp_g<<<R_TOT / 128, 512, SMEM_G>>>(gb1, gb2);

    // 3) 12 chord-mix scan steps (fp8 gathers, f16x2 mix accumulation)
    for (int m = 0; m < M_NET; ++m)
        k_scan<<<R_TOT / 16, 256>>>(m, cols, out);
}

// round 16
// speedup vs baseline: 1.2222x; 1.0077x over previous
#include <cuda_runtime.h>
#include <cuda_bf16.h>
#include <cuda_fp16.h>
#include <math.h>
#include <stdint.h>

#define R_TOT 16384
#define S_LEN 4096
#define D_DIM 128
#define K_LNK 13
#define M_NET 12
#define F8_SCALE 256.0f
#define F8_INV   0.00390625f

typedef unsigned int u32;
typedef unsigned short u16;
typedef unsigned char u8;
typedef unsigned long long u64;

// ---------------- scratch (static device memory only) ----------------------
__device__ __nv_bfloat16 g_Xhi[R_TOT * D_DIM];          // X hi, row-major
__device__ __nv_bfloat16 g_Xlo[R_TOT * D_DIM];          // X lo
__device__ __nv_bfloat16 g_B1hi[13 * 128 * 128];        // W1^T [net][n][k]
__device__ __nv_bfloat16 g_B1lo[13 * 128 * 128];
__device__ __nv_bfloat16 g_B2ghi[128 * 128];            // gW2^T [n][k]
__device__ __nv_bfloat16 g_B2glo[128 * 128];
__device__ __nv_bfloat16 g_B2fhi[12 * 16 * 128];        // fW2^T padded N=16
__device__ float g_Vres[R_TOT * D_DIM];                 // fp32 residual (exact)
__device__ u8    g_Vf8r[R_TOT * D_DIM];                 // fp8 residual seed (*256)
__device__ u8    g_Vf8a[R_TOT * D_DIM];                 // fp8 V pong (*256)
__device__ u8    g_Vf8b[R_TOT * D_DIM];                 // fp8 V ping (*256)
__device__ float g_Wall[M_NET * R_TOT * K_LNK];

// ---------------- helpers ---------------------------------------------------
__device__ __forceinline__ u32 smem_u32(const void* p) {
    u32 a;
    asm("{ .reg .u64 t; cvta.to.shared.u64 t, %1; cvt.u32.u64 %0, t; }"
        : "=r"(a) : "l"(p));
    return a;
}
__device__ __forceinline__ void ldsm4(u32* r, u32 addr) {
    asm volatile("ldmatrix.sync.aligned.m8n8.x4.shared.b16 {%0,%1,%2,%3}, [%4];"
        : "=r"(r[0]), "=r"(r[1]), "=r"(r[2]), "=r"(r[3]) : "r"(addr));
}
__device__ __forceinline__ void mma16816(float* d, const u32* a, const u32* b) {
    asm volatile(
        "mma.sync.aligned.m16n8k16.row.col.f32.bf16.bf16.f32 "
        "{%0,%1,%2,%3}, {%4,%5,%6,%7}, {%8,%9}, {%0,%1,%2,%3};"
        : "+f"(d[0]), "+f"(d[1]), "+f"(d[2]), "+f"(d[3])
        : "r"(a[0]), "r"(a[1]), "r"(a[2]), "r"(a[3]), "r"(b[0]), "r"(b[1]));
}
// swizzled byte address of 16B unit (r, c16) in a [rows][128]bf16 smem tile
__device__ __forceinline__ u32 sw_addr(u32 base, int r, int c16) {
    return base + (u32)(((r << 4) + (c16 ^ (r & 7))) << 4);
}
__device__ __forceinline__ void bf_split(float v, u16& h, u16& l) {
    __nv_bfloat16 hb = __float2bfloat16(v);
    __nv_bfloat16 lb = __float2bfloat16(v - __bfloat162float(hb));
    h = __bfloat16_as_ushort(hb);
    l = __bfloat16_as_ushort(lb);
}
// pack two fp32 -> bf16x2 (lo arg in low half = memory-first element)
__device__ __forceinline__ u32 pack_bf16x2(float lo, float hi) {
    u32 r;
    asm("cvt.rn.bf16x2.f32 %0, %1, %2;" : "=r"(r) : "f"(hi), "f"(lo));
    return r;
}
// pack two fp32 -> f16x2 (lo arg in low half)
__device__ __forceinline__ u32 f32_to_h2(float lo, float hi) {
    u32 r;
    asm("cvt.rn.f16x2.f32 %0, %1, %2;" : "=r"(r) : "f"(hi), "f"(lo));
    return r;
}
// 4 packed e4m3 (u32) -> two f16x2
__device__ __forceinline__ void f8_to_h2(u32 p, u32& a, u32& b) {
    u16 lo, hi;
    asm("mov.b32 {%0,%1}, %2;" : "=h"(lo), "=h"(hi) : "r"(p));
    asm("cvt.rn.f16x2.e4m3x2 %0, %1;" : "=r"(a) : "h"(lo));
    asm("cvt.rn.f16x2.e4m3x2 %0, %1;" : "=r"(b) : "h"(hi));
}
// f16x2 -> 2 packed e4m3
__device__ __forceinline__ u16 h2_to_f8(u32 h2) {
    u16 r;
    asm("cvt.rn.satfinite.e4m3x2.f16x2 %0, %1;" : "=h"(r) : "r"(h2));
    return r;
}
__device__ __forceinline__ u32 pack_u16x2(u16 a, u16 b) {
    u32 r;
    asm("mov.b32 %0, {%1,%2};" : "=r"(r) : "h"(a), "h"(b));
    return r;
}
__device__ __forceinline__ void hfma2(u32& d, u32 a, u32 b) {
    asm("fma.rn.f16x2 %0, %1, %2, %0;" : "+r"(d) : "r"(a), "r"(b));
}
__device__ __forceinline__ u32 hadd2(u32 a, u32 b) {
    u32 r;
    asm("add.rn.f16x2 %0, %1, %2;" : "=r"(r) : "r"(a), "r"(b));
    return r;
}
__device__ __forceinline__ float gelu_exact(float x) {
    return 0.5f * x * (1.0f + erff(x * 0.70710678118654752440f));
}

// ---------------------------------------------------------------------------
// Fused init: weight prep (transpose + bf16 split) + embeddings.
// ---------------------------------------------------------------------------
#define PREP_A (13 * 128 * 64)
#define PREP_B (128 * 64)
#define PREP_C (12 * 16 * 64)
#define PREP_TOT (PREP_A + PREP_B + PREP_C)
#define EMB_TOT (R_TOT * 16)
#define INIT_TOT (PREP_TOT + EMB_TOT)

__global__ void k_init(const float* __restrict__ gW1,
                       const float* __restrict__ gW2,
                       const float* __restrict__ fW1,
                       const float* __restrict__ fW2,
                       const int* __restrict__ data,
                       const float* __restrict__ emb,
                       const float* __restrict__ apc) {
    int t = blockIdx.x * blockDim.x + threadIdx.x;
    if (t < PREP_TOT) {
        float w0, w1;
        if (t < PREP_A) {
            int net = t >> 13;
            int r = t & 8191;
            int n = r >> 6, k = (r & 63) * 2;
            const float* W1 = (net == 0) ? gW1
                                         : fW1 + (size_t)(net - 1) * 128 * 128;
            w0 = W1[k * 128 + n];
            w1 = W1[(k + 1) * 128 + n];
            int widx = (net * 128 + n) * 64 + (k >> 1);
            u16 h0, l0, h1, l1;
            bf_split(w0, h0, l0); bf_split(w1, h1, l1);
            ((u32*)g_B1hi)[widx] = (u32)h0 | ((u32)h1 << 16);
            ((u32*)g_B1lo)[widx] = (u32)l0 | ((u32)l1 << 16);
        } else if (t < PREP_A + PREP_B) {
            int r = t - PREP_A;
            int n = r >> 6, k = (r & 63) * 2;
            w0 = gW2[k * 128 + n];
            w1 = gW2[(k + 1) * 128 + n];
            int widx = n * 64 + (k >> 1);
            u16 h0, l0, h1, l1;
            bf_split(w0, h0, l0); bf_split(w1, h1, l1);
            ((u32*)g_B2ghi)[widx] = (u32)h0 | ((u32)h1 << 16);
            ((u32*)g_B2glo)[widx] = (u32)l0 | ((u32)l1 << 16);
        } else {
            int r = t - PREP_A - PREP_B;
            int net = r >> 10;
            int rr = r & 1023;
            int n = rr >> 6, k = (rr & 63) * 2;
            w0 = (n < 13) ? fW2[(size_t)net * 128 * 13 + k * 13 + n] : 0.0f;
            w1 = (n < 13) ? fW2[(size_t)net * 128 * 13 + (k + 1) * 13 + n] : 0.0f;
            ((u32*)g_B2fhi)[(net * 16 + n) * 64 + (k >> 1)] =
                pack_bf16x2(w0, w1);
        }
    } else {
        int idx = t - PREP_TOT;
        if (idx >= EMB_TOT) return;
        int row = idx >> 4;
        int g8 = idx & 15;
        int tok = data[row];
        int s = row & (S_LEN - 1);
        float4 e0 = ((const float4*)emb)[tok * 32 + g8 * 2];
        float4 e1 = ((const float4*)emb)[tok * 32 + g8 * 2 + 1];
        float4 a0 = ((const float4*)apc)[s * 32 + g8 * 2];
        float4 a1 = ((const float4*)apc)[s * 32 + g8 * 2 + 1];
        float v[8] = {e0.x + a0.x, e0.y + a0.y, e0.z + a0.z, e0.w + a0.w,
                      e1.x + a1.x, e1.y + a1.y, e1.z + a1.z, e1.w + a1.w};
        u32 hp[4], lp[4];
        #pragma unroll
        for (int p = 0; p < 4; ++p) {
            u16 h0, l0, h1, l1;
            bf_split(v[2 * p], h0, l0);
            bf_split(v[2 * p + 1], h1, l1);
            hp[p] = (u32)h0 | ((u32)h1 << 16);
            lp[p] = (u32)l0 | ((u32)l1 << 16);
        }
        ((uint4*)g_Xhi)[row * 16 + g8] = make_uint4(hp[0], hp[1], hp[2], hp[3]);
        ((uint4*)g_Xlo)[row * 16 + g8] = make_uint4(lp[0], lp[1], lp[2], lp[3]);
    }
}

// ---------------------------------------------------------------------------
// k_mlp_g: g-net only (3-term bf16 hi/lo split, fp32 backbone).
// grid = 128 row-tiles, 512 threads, 132 KB smem (1 CTA/SM).
// ---------------------------------------------------------------------------
#define G_W1HI  0
#define G_W1LO  32768
#define G_XHHI  65536
#define G_XHLO  98304
#define G_B1S   131072
#define G_B2S   131584
#define SMEM_G  132096

extern __shared__ char smc[];

__global__ void __launch_bounds__(512, 1) k_mlp_g(
    const float* __restrict__ gb1, const float* __restrict__ gb2) {
    const int tid = threadIdx.x;
    const int lane = tid & 31;
    const int wid = tid >> 5;
    const int row0 = blockIdx.x * 128;
    const u32 sbase = smem_u32(smc);
    float* b1s = (float*)(smc + G_B1S);
    float* b2s = (float*)(smc + G_B2S);

    {
        const uint4* s1h = (const uint4*)g_B1hi;
        const uint4* s1l = (const uint4*)g_B1lo;
        const uint4* sxh = (const uint4*)g_Xhi + row0 * 16;
        const uint4* sxl = (const uint4*)g_Xlo + row0 * 16;
        #pragma unroll
        for (int p = 0; p < 4; ++p) {
            int q = tid + p * 512;
            int r = q >> 4, c16 = q & 15;
            u32 d = (u32)(((r << 4) + (c16 ^ (r & 7))) << 4);
            *(uint4*)(smc + G_W1HI + d) = s1h[q];
            *(uint4*)(smc + G_W1LO + d) = s1l[q];
            *(uint4*)(smc + G_XHHI + d) = sxh[q];
            *(uint4*)(smc + G_XHLO + d) = sxl[q];
        }
    }
    if (tid < 128) { b1s[tid] = gb1[tid]; b2s[tid] = gb2[tid]; }
    __syncthreads();

    const int a_ro = (lane & 7) + (lane & 8);
    const int a_co = lane >> 4;
    const int b_ro = (lane & 7) + ((lane >> 1) & 8);
    const int b_co = (lane >> 3) & 1;
    const int tq = lane >> 2;
    const int tr = (lane & 3) * 2;
    const int wm = (wid & 3) * 32;
    const int wn = (wid >> 2) * 32;

    // Layer 1 (3-term split)
    float acc[2][4][4];
    #pragma unroll
    for (int i = 0; i < 2; ++i)
        #pragma unroll
        for (int j = 0; j < 4; ++j)
            #pragma unroll
            for (int q = 0; q < 4; ++q) acc[i][j][q] = 0.0f;

    #pragma unroll
    for (int k = 0; k < 8; ++k) {
        const int kc = k * 2;
        u32 ah[2][4], al[2][4], bh[2][4], bl[2][4];
        #pragma unroll
        for (int mt = 0; mt < 2; ++mt) {
            int r = wm + mt * 16 + a_ro;
            ldsm4(ah[mt], sw_addr(sbase + G_XHHI, r, kc + a_co));
            ldsm4(al[mt], sw_addr(sbase + G_XHLO, r, kc + a_co));
        }
        #pragma unroll
        for (int ng = 0; ng < 2; ++ng) {
            int r = wn + ng * 16 + b_ro;
            ldsm4(bh[ng], sw_addr(sbase + G_W1HI, r, kc + b_co));
            ldsm4(bl[ng], sw_addr(sbase + G_W1LO, r, kc + b_co));
        }
        #pragma unroll
        for (int mt = 0; mt < 2; ++mt)
            #pragma unroll
            for (int ng = 0; ng < 2; ++ng) {
                mma16816(acc[mt][2 * ng],     ah[mt], &bh[ng][0]);
                mma16816(acc[mt][2 * ng + 1], ah[mt], &bh[ng][2]);
                mma16816(acc[mt][2 * ng],     ah[mt], &bl[ng][0]);
                mma16816(acc[mt][2 * ng + 1], ah[mt], &bl[ng][2]);
                mma16816(acc[mt][2 * ng],     al[mt], &bh[ng][0]);
                mma16816(acc[mt][2 * ng + 1], al[mt], &bh[ng][2]);
            }
    }
    __syncthreads();

    // epilogue 1: bias + gelu + hi/lo split -> XH regions
    #pragma unroll
    for (int mt = 0; mt < 2; ++mt)
        #pragma unroll
        for (int nt = 0; nt < 4; ++nt) {
            int r = wm + mt * 16 + tq;
            int c = wn + nt * 8 + tr;
            float v0 = gelu_exact(acc[mt][nt][0] + b1s[c]);
            float v1 = gelu_exact(acc[mt][nt][1] + b1s[c + 1]);
            float v2 = gelu_exact(acc[mt][nt][2] + b1s[c]);
            float v3 = gelu_exact(acc[mt][nt][3] + b1s[c + 1]);
            int c16 = c >> 3, cb = (c & 7) * 2;
            u32 d0 = sw_addr(sbase + G_XHHI, r, c16) - sbase + cb;
            u32 d8 = sw_addr(sbase + G_XHHI, r + 8, c16) - sbase + cb;
            u16 h0, l0, h1, l1, h2, l2, h3, l3;
            bf_split(v0, h0, l0); bf_split(v1, h1, l1);
            bf_split(v2, h2, l2); bf_split(v3, h3, l3);
            *(u32*)(smc + d0) = (u32)h0 | ((u32)h1 << 16);
            *(u32*)(smc + d8) = (u32)h2 | ((u32)h3 << 16);
            *(u32*)(smc + d0 + (G_XHLO - G_XHHI)) = (u32)l0 | ((u32)l1 << 16);
            *(u32*)(smc + d8 + (G_XHLO - G_XHHI)) = (u32)l2 | ((u32)l3 << 16);
        }

    // restage gW2^T over W1
    {
        const uint4* s2h = (const uint4*)g_B2ghi;
        const uint4* s2l = (const uint4*)g_B2glo;
        #pragma unroll
        for (int p = 0; p < 4; ++p) {
            int q = tid + p * 512;
            int r = q >> 4, c16 = q & 15;
            u32 d = (u32)(((r << 4) + (c16 ^ (r & 7))) << 4);
            *(uint4*)(smc + G_W1HI + d) = s2h[q];
            *(uint4*)(smc + G_W1LO + d) = s2l[q];
        }
    }
    __syncthreads();

    // Layer 2 (3-term split)
    float ac2[2][4][4];
    #pragma unroll
    for (int i = 0; i < 2; ++i)
        #pragma unroll
        for (int j = 0; j < 4; ++j)
            #pragma unroll
            for (int q = 0; q < 4; ++q) ac2[i][j][q] = 0.0f;
    #pragma unroll
    for (int k = 0; k < 8; ++k) {
        const int kc = k * 2;
        u32 ah[2][4], al[2][4], bh[2][4], bl[2][4];
        #pragma unroll
        for (int mt = 0; mt < 2; ++mt) {
            int r = wm + mt * 16 + a_ro;
            ldsm4(ah[mt], sw_addr(sbase + G_XHHI, r, kc + a_co));
            ldsm4(al[mt], sw_addr(sbase + G_XHLO, r, kc + a_co));
        }
        #pragma unroll
        for (int ng = 0; ng < 2; ++ng) {
            int r = wn + ng * 16 + b_ro;
            ldsm4(bh[ng], sw_addr(sbase + G_W1HI, r, kc + b_co));
            ldsm4(bl[ng], sw_addr(sbase + G_W1LO, r, kc + b_co));
        }
        #pragma unroll
        for (int mt = 0; mt < 2; ++mt)
            #pragma unroll
            for (int ng = 0; ng < 2; ++ng) {
                mma16816(ac2[mt][2 * ng],     ah[mt], &bh[ng][0]);
                mma16816(ac2[mt][2 * ng + 1], ah[mt], &bh[ng][2]);
                mma16816(ac2[mt][2 * ng],     ah[mt], &bl[ng][0]);
                mma16816(ac2[mt][2 * ng + 1], ah[mt], &bl[ng][2]);
                mma16816(ac2[mt][2 * ng],     al[mt], &bh[ng][0]);
                mma16816(ac2[mt][2 * ng + 1], al[mt], &bh[ng][2]);
            }
    }
    #pragma unroll
    for (int mt = 0; mt < 2; ++mt)
        #pragma unroll
        for (int nt = 0; nt < 4; ++nt) {
            int r = wm + mt * 16 + tq;
            int c = wn + nt * 8 + tr;
            float2 o0 = make_float2(ac2[mt][nt][0] + b2s[c],
                                    ac2[mt][nt][1] + b2s[c + 1]);
            float2 o1 = make_float2(ac2[mt][nt][2] + b2s[c],
                                    ac2[mt][nt][3] + b2s[c + 1]);
            size_t i0 = (size_t)(row0 + r) * 128 + c;
            size_t i1 = (size_t)(row0 + r + 8) * 128 + c;
            *(float2*)(g_Vres + i0) = o0;
            *(float2*)(g_Vres + i1) = o1;
            // fp8 residual seed (also step-0 gather source), scaled by 256
            u32 hs0 = f32_to_h2(o0.x * F8_SCALE, o0.y * F8_SCALE);
            u32 hs1 = f32_to_h2(o1.x * F8_SCALE, o1.y * F8_SCALE);
            *(u16*)(g_Vf8r + i0) = h2_to_f8(hs0);
            *(u16*)(g_Vf8r + i1) = h2_to_f8(hs1);
        }
}

// ---------------------------------------------------------------------------
// k_mlp_f: f-nets (single-term bf16). Compact smem (~70 KB) -> 2 CTAs/SM.
// grid = (128 row-tiles, 12 nets), 512 threads.
// ---------------------------------------------------------------------------
#define F_W1HI  0
#define F_XHHI  32768
#define F_F2HI  65536
#define F_B1S   69632
#define F_B2S   70144
#define SMEM_F  70656

__global__ void __launch_bounds__(512, 2) k_mlp_f(
    const float* __restrict__ fb1, const float* __restrict__ fb2) {
    const int tid = threadIdx.x;
    const int lane = tid & 31;
    const int wid = tid >> 5;
    const int m = blockIdx.y;               // 0..11 (f-net index)
    const int row0 = blockIdx.x * 128;
    const u32 sbase = smem_u32(smc);
    float* b1s = (float*)(smc + F_B1S);
    float* b2s = (float*)(smc + F_B2S);

    {
        const uint4* s1h = (const uint4*)g_B1hi + (m + 1) * 2048;
        const uint4* sxh = (const uint4*)g_Xhi + row0 * 16;
        #pragma unroll
        for (int p = 0; p < 4; ++p) {
            int q = tid + p * 512;
            int r = q >> 4, c16 = q & 15;
            u32 d = (u32)(((r << 4) + (c16 ^ (r & 7))) << 4);
            *(uint4*)(smc + F_W1HI + d) = s1h[q];
            *(uint4*)(smc + F_XHHI + d) = sxh[q];
        }
    }
    {
        const uint4* sfh = (const uint4*)g_B2fhi + m * 256;
        if (tid < 256) {
            int r = tid >> 4, c16 = tid & 15;
            u32 d = (u32)(((r << 4) + (c16 ^ (r & 7))) << 4);
            *(uint4*)(smc + F_F2HI + d) = sfh[tid];
        }
        if (tid < 128) b1s[tid] = fb1[m * 128 + tid];
        if (tid < 16)  b2s[tid] = (tid < 13) ? fb2[m * 13 + tid] : 0.0f;
    }
    __syncthreads();

    const int a_ro = (lane & 7) + (lane & 8);
    const int a_co = lane >> 4;
    const int b_ro = (lane & 7) + ((lane >> 1) & 8);
    const int b_co = (lane >> 3) & 1;
    const int tq = lane >> 2;
    const int tr = (lane & 3) * 2;
    const int wm = (wid & 3) * 32;
    const int wn = (wid >> 2) * 32;

    // Layer 1 (single term)
    float acc[2][4][4];
    #pragma unroll
    for (int i = 0; i < 2; ++i)
        #pragma unroll
        for (int j = 0; j < 4; ++j)
            #pragma unroll
            for (int q = 0; q < 4; ++q) acc[i][j][q] = 0.0f;
    #pragma unroll
    for (int k = 0; k < 8; ++k) {
        const int kc = k * 2;
        u32 ah[2][4], bh[2][4];
        #pragma unroll
        for (int mt = 0; mt < 2; ++mt)
            ldsm4(ah[mt], sw_addr(sbase + F_XHHI, wm + mt * 16 + a_ro, kc + a_co));
        #pragma unroll
        for (int ng = 0; ng < 2; ++ng)
            ldsm4(bh[ng], sw_addr(sbase + F_W1HI, wn + ng * 16 + b_ro, kc + b_co));
        #pragma unroll
        for (int mt = 0; mt < 2; ++mt)
            #pragma unroll
            for (int ng = 0; ng < 2; ++ng) {
                mma16816(acc[mt][2 * ng],     ah[mt], &bh[ng][0]);
                mma16816(acc[mt][2 * ng + 1], ah[mt], &bh[ng][2]);
            }
    }
    __syncthreads();

    // epilogue 1: bias + gelu -> H (bf16) over X region
    #pragma unroll
    for (int mt = 0; mt < 2; ++mt)
        #pragma unroll
        for (int nt = 0; nt < 4; ++nt) {
            int r = wm + mt * 16 + tq;
            int c = wn + nt * 8 + tr;
            float v0 = gelu_exact(acc[mt][nt][0] + b1s[c]);
            float v1 = gelu_exact(acc[mt][nt][1] + b1s[c + 1]);
            float v2 = gelu_exact(acc[mt][nt][2] + b1s[c]);
            float v3 = gelu_exact(acc[mt][nt][3] + b1s[c + 1]);
            int c16 = c >> 3, cb = (c & 7) * 2;
            u32 d0 = sw_addr(sbase + F_XHHI, r, c16) - sbase + cb;
            u32 d8 = sw_addr(sbase + F_XHHI, r + 8, c16) - sbase + cb;
            *(u32*)(smc + d0) = pack_bf16x2(v0, v1);
            *(u32*)(smc + d8) = pack_bf16x2(v2, v3);
        }
    __syncthreads();

    // Layer 2: W_all = H @ fW2 (N=16 padded), warps 0-7
    if (wid < 8) {
        const int wm2 = wid * 16;
        float ac2[2][4];
        #pragma unroll
        for (int j = 0; j < 2; ++j)
            #pragma unroll
            for (int q = 0; q < 4; ++q) ac2[j][q] = 0.0f;
        #pragma unroll
        for (int k = 0; k < 8; ++k) {
            const int kc = k * 2;
            u32 ah[4], bh[4];
            ldsm4(ah, sw_addr(sbase + F_XHHI, wm2 + a_ro, kc + a_co));
            ldsm4(bh, sw_addr(sbase + F_F2HI, b_ro, kc + b_co));
            mma16816(ac2[0], ah, &bh[0]);
            mma16816(ac2[1], ah, &bh[2]);
        }
        float* op = g_Wall + (size_t)m * R_TOT * K_LNK + (size_t)row0 * K_LNK;
        #pragma unroll
        for (int nt = 0; nt < 2; ++nt) {
            int c = nt * 8 + tr;
            int r = wm2 + tq;
            if (c < 13) {
                op[(r) * K_LNK + c]     = ac2[nt][0] + b2s[c];
                op[(r + 8) * K_LNK + c] = ac2[nt][2] + b2s[c];
            }
            if (c + 1 < 13) {
                op[(r) * K_LNK + c + 1]     = ac2[nt][1] + b2s[c + 1];
                op[(r + 8) * K_LNK + c + 1] = ac2[nt][3] + b2s[c + 1];
            }
        }
    }
}

// ---------------------------------------------------------------------------
// k_scan: chord-mix step with fp8 gathers (scaled by 256), f16x2 mix accum.
// TWO rows per warp. Gathers issued in two register-resident batches (7 + 6)
// to raise memory-level parallelism; launch_bounds(256, 5) grants ~48 regs.
// Intermediate: out_f8 = f8(h2(f8res) + acc). Final: fp32 res + acc/256.
// ---------------------------------------------------------------------------
__global__ void __launch_bounds__(256, 5) k_scan(int m, const int* __restrict__ cols,
                                                 float* __restrict__ out_final) {
    const u8* Vin = (m == 0) ? g_Vf8r : ((m & 1) ? g_Vf8b : g_Vf8a);
    u8* Vout = (m & 1) ? g_Vf8a : g_Vf8b;
    const float* Wm = g_Wall + (size_t)m * R_TOT * K_LNK;

    const int lane = threadIdx.x & 31;
    const int pair = (blockIdx.x * blockDim.x + threadIdx.x) >> 5;
    const int hl   = lane & 15;
    const int lr   = pair * 2 + (lane >> 4);

    u32 wv = 0; int iv = 0;
    if (hl < K_LNK) {
        float w = Wm[lr * K_LNK + hl];
        wv = f32_to_h2(w, w);
        int s = lr & (S_LEN - 1), b = lr >> 12;
        iv = ((b << 12) | cols[s * K_LNK + hl]) << 4;  // uint2 row base (16/row)
    }

    const uint2* Vin2 = (const uint2*)Vin;
    u32 a0 = 0, a1 = 0, a2 = 0, a3 = 0;     // f16x2 mix accumulators (*256)
    const int selk = lane & 16;

    // batch 1: links 0..6 (all 7 loads in flight)
    {
        u32 wk[7]; uint2 v[7];
        #pragma unroll
        for (int j = 0; j < 7; ++j) {
            wk[j] = __shfl_sync(0xffffffffu, wv, j | selk);
            int ik = __shfl_sync(0xffffffffu, iv, j | selk);
            v[j] = Vin2[ik + hl];
        }
        #pragma unroll
        for (int j = 0; j < 7; ++j) {
            u32 h0, h1, h2, h3;
            f8_to_h2(v[j].x, h0, h1);
            f8_to_h2(v[j].y, h2, h3);
            hfma2(a0, h0, wk[j]);
            hfma2(a1, h1, wk[j]);
            hfma2(a2, h2, wk[j]);
            hfma2(a3, h3, wk[j]);
        }
    }
    // batch 2: links 7..12 (6 loads in flight)
    {
        u32 wk[6]; uint2 v[6];
        #pragma unroll
        for (int j = 0; j < 6; ++j) {
            wk[j] = __shfl_sync(0xffffffffu, wv, (j + 7) | selk);
            int ik = __shfl_sync(0xffffffffu, iv, (j + 7) | selk);
            v[j] = Vin2[ik + hl];
        }
        #pragma unroll
        for (int j = 0; j < 6; ++j) {
            u32 h0, h1, h2, h3;
            f8_to_h2(v[j].x, h0, h1);
            f8_to_h2(v[j].y, h2, h3);
            hfma2(a0, h0, wk[j]);
            hfma2(a1, h1, wk[j]);
            hfma2(a2, h2, wk[j]);
            hfma2(a3, h3, wk[j]);
        }
    }

    if (m == M_NET - 1) {
        const float4* res4 = (const float4*)g_Vres + ((size_t)lr << 5);
        float4 r0 = res4[hl * 2], r1 = res4[hl * 2 + 1];
        float2 f0 = __half22float2(*(__half2*)&a0);
        float2 f1 = __half22float2(*(__half2*)&a1);
        float2 f2 = __half22float2(*(__half2*)&a2);
        float2 f3 = __half22float2(*(__half2*)&a3);
        r0.x += f0.x * F8_INV; r0.y += f0.y * F8_INV;
        r0.z += f1.x * F8_INV; r0.w += f1.y * F8_INV;
        r1.x += f2.x * F8_INV; r1.y += f2.y * F8_INV;
        r1.z += f3.x * F8_INV; r1.w += f3.y * F8_INV;
        float4* op = (float4*)out_final + ((size_t)lr << 5);
        op[hl * 2]     = r0;
        op[hl * 2 + 1] = r1;
    } else {
        uint2 rr = ((const uint2*)g_Vf8r)[((size_t)lr << 4) + hl];
        u32 r0, r1, r2, r3;
        f8_to_h2(rr.x, r0, r1);
        f8_to_h2(rr.y, r2, r3);
        u16 s0 = h2_to_f8(hadd2(r0, a0));
        u16 s1 = h2_to_f8(hadd2(r1, a1));
        u16 s2 = h2_to_f8(hadd2(r2, a2));
        u16 s3 = h2_to_f8(hadd2(r3, a3));
        uint2 ov;
        ov.x = pack_u16x2(s0, s1);
        ov.y = pack_u16x2(s2, s3);
        ((uint2*)Vout)[((size_t)lr << 4) + hl] = ov;
    }
}

// ---------------------------------------------------------------------------
extern "C" void kernel_launch(void* const* d_in, const int* in_sizes, int n_in,
                              void* d_out, int out_size) {
    const int*   data = (const int*)  d_in[0];
    const int*   cols = (const int*)  d_in[1];
    const float* emb  = (const float*)d_in[2];
    const float* apc  = (const float*)d_in[3];
    const float* gW1  = (const float*)d_in[4];
    const float* gb1  = (const float*)d_in[5];
    const float* gW2  = (const float*)d_in[6];
    const float* gb2  = (const float*)d_in[7];
    const float* fW1  = (const float*)d_in[8];
    const float* fb1  = (const float*)d_in[9];
    const float* fW2  = (const float*)d_in[10];
    const float* fb2  = (const float*)d_in[11];
    float* out = (float*)d_out;

    cudaFuncSetAttribute(k_mlp_g, cudaFuncAttributeMaxDynamicSharedMemorySize,
                         SMEM_G);
    cudaFuncSetAttribute(k_mlp_f, cudaFuncAttributeMaxDynamicSharedMemorySize,
                         SMEM_F);

    // 1) fused weight prep + embeddings
    k_init<<<(INIT_TOT + 255) / 256, 256>>>(gW1, gW2, fW1, fW2,
                                            data, emb, apc);

    // 2) f-nets (2 CTAs/SM) then g-net (1 CTA/SM)
    dim3 grid_f(R_TOT / 128, 12);
    k_mlp_f<<<grid_f, 512, SMEM_F>>>(fb1, fb2);
    k_mlp_g<<<R_TOT / 128, 512, SMEM_G>>>(gb1, gb2);

    // 3) 12 chord-mix scan steps (fp8 gathers, batched MLP=7)
    for (int m = 0; m < M_NET; ++m)
        k_scan<<<R_TOT / 16, 256>>>(m, cols, out);
}